// round 8
// baseline (speedup 1.0000x reference)
#include <cuda_runtime.h>
#include <math.h>
#include <stdint.h>

#define B_    64
#define CIN   96
#define CMID  576
#define COUT  96
#define HW_   784
#define NPIX  (B_*HW_)
#define NBITF 127.0f

__device__ float g_s[4];
__device__ float g_ws1[CMID], g_bf1[CMID];
__device__ float g_ws2[CMID], g_bf2[CMID];
__device__ float g_ws3[COUT], g_bf3[COUT];
__device__ __align__(16) int g_w1p[CMID * 24];    // [co][24 kwords]
__device__ __align__(16) int g_w2p[CMID * 3];
__device__ __align__(16) int g_w3p[COUT * 144];   // [co][144 kwords]
__device__ __align__(16) signed char g_y1[B_ * CMID * HW_];   // channel-major
__device__ __align__(16) int g_y2i[B_ * 144 * HW_];           // interleaved: word(b,cg,hw)=ch 4cg..4cg+3

// ---------------- cp.async helpers ----------------
__device__ __forceinline__ uint32_t smem_u32(const void* p) {
    uint32_t a;
    asm("{ .reg .u64 t; cvta.to.shared.u64 t, %1; cvt.u32.u64 %0, t; }" : "=r"(a) : "l"(p));
    return a;
}
#define CP16(dst, src) \
    asm volatile("cp.async.cg.shared.global [%0], [%1], 16;" :: "r"(dst), "l"(src))
#define CP_COMMIT() asm volatile("cp.async.commit_group;")
#define CP_WAIT0()  asm volatile("cp.async.wait_group 0;")
#define CP_WAIT1()  asm volatile("cp.async.wait_group 1;")

// ---------------- prep: scales + BN fold + weight quant + pack ----------------
__global__ void __launch_bounds__(256) prep_all(
    const float* __restrict__ w1, const float* __restrict__ g1, const float* __restrict__ b1,
    const float* __restrict__ m1, const float* __restrict__ v1,
    const float* __restrict__ w2, const float* __restrict__ g2, const float* __restrict__ b2,
    const float* __restrict__ m2, const float* __restrict__ v2,
    const float* __restrict__ w3, const float* __restrict__ g3, const float* __restrict__ b3,
    const float* __restrict__ m3, const float* __restrict__ v3,
    const float* __restrict__ r0, const float* __restrict__ r1,
    const float* __restrict__ r2, const float* __restrict__ r3,
    const int* __restrict__ cl, float* s3out) {
    __shared__ float sv[8][CMID];
    __shared__ signed char qs[8][CMID];
    const int w = threadIdx.x >> 5, lane = threadIdx.x & 31;
    const int gw = blockIdx.x * 8 + w;

    if (blockIdx.x == 0 && threadIdx.x == 0) {
        int c = cl[0];
        g_s[0] = r0[c] / NBITF;
        g_s[1] = r1[c] / NBITF;
        g_s[2] = r2[c] / NBITF;
        float s3 = r3[c] / NBITF;
        g_s[3] = s3;
        if (s3out) *s3out = s3;
    }

    if (gw < CMID) {
        int co = gw;
        float scale = g1[co] / sqrtf(v1[co] + 1e-5f);
        float m = 0.f;
        for (int k = lane; k < CIN; k += 32) {
            float v = w1[co * CIN + k] * scale;
            sv[w][k] = v;
            m = fmaxf(m, fabsf(v));
        }
        #pragma unroll
        for (int s = 16; s > 0; s >>= 1) m = fmaxf(m, __shfl_xor_sync(0xFFFFFFFF, m, s));
        float sc = m / NBITF;
        if (lane == 0) { g_ws1[co] = sc; g_bf1[co] = b1[co] - m1[co] * scale; }
        for (int k = lane; k < CIN; k += 32) {
            float q = fminf(fmaxf(rintf(sv[w][k] / sc), -127.f), 127.f);
            qs[w][k] = (signed char)q;
        }
        __syncwarp();
        if (lane < 24) {
            const signed char* q = &qs[w][4 * lane];
            g_w1p[co * 24 + lane] = (q[0] & 0xFF) | ((q[1] & 0xFF) << 8) |
                                    ((q[2] & 0xFF) << 16) | ((q[3] & 0xFF) << 24);
        }
    } else if (gw < 2 * CMID) {
        int co = gw - CMID;
        float scale = g2[co] / sqrtf(v2[co] + 1e-5f);
        float m = 0.f;
        if (lane < 9) {
            float v = w2[co * 9 + lane] * scale;
            sv[w][lane] = v;
            m = fabsf(v);
        }
        #pragma unroll
        for (int s = 16; s > 0; s >>= 1) m = fmaxf(m, __shfl_xor_sync(0xFFFFFFFF, m, s));
        float sc = m / NBITF;
        if (lane == 0) { g_ws2[co] = sc; g_bf2[co] = b2[co] - m2[co] * scale; }
        if (lane < 9) {
            float q = fminf(fmaxf(rintf(sv[w][lane] / sc), -127.f), 127.f);
            qs[w][lane] = (signed char)q;
        }
        __syncwarp();
        if (lane < 3) {
            const signed char* q = &qs[w][3 * lane];
            g_w2p[co * 3 + lane] = (q[0] & 0xFF) | ((q[1] & 0xFF) << 8) | ((q[2] & 0xFF) << 16);
        }
    } else {
        int co = gw - 2 * CMID;
        float scale = g3[co] / sqrtf(v3[co] + 1e-5f);
        float m = 0.f;
        for (int k = lane; k < CMID; k += 32) {
            float v = w3[co * CMID + k] * scale;
            sv[w][k] = v;
            m = fmaxf(m, fabsf(v));
        }
        #pragma unroll
        for (int s = 16; s > 0; s >>= 1) m = fmaxf(m, __shfl_xor_sync(0xFFFFFFFF, m, s));
        float sc = m / NBITF;
        if (lane == 0) { g_ws3[co] = sc; g_bf3[co] = b3[co] - m3[co] * scale; }
        for (int k = lane; k < CMID; k += 32) {
            float q = fminf(fmaxf(rintf(sv[w][k] / sc), -127.f), 127.f);
            qs[w][k] = (signed char)q;
        }
        __syncwarp();
        for (int p = lane; p < 144; p += 32) {
            const signed char* q = &qs[w][4 * p];
            g_w3p[co * 144 + p] = (q[0] & 0xFF) | ((q[1] & 0xFF) << 8) |
                                  ((q[2] & 0xFF) << 16) | ((q[3] & 0xFF) << 24);
        }
    }
}

// ---------------- IMMA + requant ----------------
__device__ __forceinline__ void mma_s8(int& d0, int& d1, int& d2, int& d3,
                                       int a0, int a1, int a2, int a3,
                                       int b0, int b1) {
    asm volatile(
        "mma.sync.aligned.m16n8k32.row.col.s32.s8.s8.s32 "
        "{%0,%1,%2,%3}, {%4,%5,%6,%7}, {%8,%9}, {%0,%1,%2,%3};"
        : "+r"(d0), "+r"(d1), "+r"(d2), "+r"(d3)
        : "r"(a0), "r"(a1), "r"(a2), "r"(a3), "r"(b0), "r"(b1));
}
__device__ __forceinline__ int requant_sat(int acc, float al6, float bb6, float C) {
    float z = __saturatef(fmaf((float)acc, al6, bb6));
    int q = __float2int_rn(z * C);
    return q > 127 ? 127 : q;
}

// ---------------- k1: quant(x) + 1x1 conv (96->576) IMMA, pipelined weights ----------------
#define AS1 136
#define WS  28
__global__ void __launch_bounds__(256, 3) k1_conv1(const float* __restrict__ x) {
    __shared__ __align__(16) int a_sm[24 * AS1];       // 13056 B
    __shared__ __align__(16) int w_sm[2][96 * WS];     // 21504 B
    __shared__ float s_al[CMID], s_bb[CMID];           // 4608 B
    __shared__ __align__(16) signed char o_sm[8 * 512];

    const int tid = threadIdx.x;
    const int n0 = blockIdx.x * 128;
    const float s0 = g_s[0];
    const float inv_s0 = 1.0f / s0;
    const float C1 = 6.0f / g_s[1];
    const float SIXTH = 1.0f / 6.0f;

    // prologue: weight chunk 0 (co 0..95)
    for (int idx = tid; idx < 576; idx += 256) {
        int co = idx / 6, seg = idx % 6;
        CP16(smem_u32(&w_sm[0][co * WS + 4 * seg]), &g_w1p[co * 24 + 4 * seg]);
    }
    CP_COMMIT();

    // alpha/beta tables (all 576)
    for (int i = tid; i < CMID; i += 256) {
        s_al[i] = (s0 * g_ws1[i]) * SIXTH;
        s_bb[i] = g_bf1[i] * SIXTH;
    }

    // quantize x tile (96ch x 128px) into k-packed smem
    for (int idx = tid; idx < 768; idx += 256) {
        int cg = idx >> 5, q4 = idx & 31;
        int n = n0 + 4 * q4;
        int b = n / HW_;
        int hw = n - b * HW_;
        int q[4][4];
        #pragma unroll
        for (int j = 0; j < 4; ++j) {
            float4 v = *(const float4*)(x + ((size_t)(b * CIN + 4 * cg + j) * HW_ + hw));
            float f;
            f = fminf(fmaxf(rintf(v.x * inv_s0), -127.f), 127.f); q[j][0] = (int)f;
            f = fminf(fmaxf(rintf(v.y * inv_s0), -127.f), 127.f); q[j][1] = (int)f;
            f = fminf(fmaxf(rintf(v.z * inv_s0), -127.f), 127.f); q[j][2] = (int)f;
            f = fminf(fmaxf(rintf(v.w * inv_s0), -127.f), 127.f); q[j][3] = (int)f;
        }
        int w[4];
        #pragma unroll
        for (int p = 0; p < 4; ++p) {
            int lo = __byte_perm(q[0][p], q[1][p], 0x0040);
            int hi = __byte_perm(q[2][p], q[3][p], 0x0040);
            w[p] = __byte_perm(lo, hi, 0x5410);
        }
        *(int4*)&a_sm[cg * AS1 + 4 * q4] = make_int4(w[0], w[1], w[2], w[3]);
    }

    const int lane = tid & 31, wid = tid >> 5;
    const int g = lane >> 2, tg = lane & 3;
    const int p0 = wid * 16;
    const int nn = n0 + p0;
    const int bw = nn / HW_;
    const int hww = nn - bw * HW_;

    __syncthreads();

    // per-warp A fragments (all K=96)
    int A0[3], A1[3], A2[3], A3[3];
    #pragma unroll
    for (int s = 0; s < 3; ++s) {
        A0[s] = a_sm[(8 * s + tg) * AS1 + p0 + g];
        A1[s] = a_sm[(8 * s + tg) * AS1 + p0 + g + 8];
        A2[s] = a_sm[(8 * s + 4 + tg) * AS1 + p0 + g];
        A3[s] = a_sm[(8 * s + 4 + tg) * AS1 + p0 + g + 8];
    }

    for (int kc = 0; kc < 6; ++kc) {       // 6 chunks of 96 output channels
        __syncthreads();                   // everyone done reading buf (kc+1)&1
        if (kc < 5) {
            for (int idx = tid; idx < 576; idx += 256) {
                int co = idx / 6, seg = idx % 6;
                CP16(smem_u32(&w_sm[(kc + 1) & 1][co * WS + 4 * seg]),
                     &g_w1p[((kc + 1) * 96 + co) * 24 + 4 * seg]);
            }
            CP_COMMIT();
            CP_WAIT1();
        } else {
            CP_WAIT0();
        }
        __syncthreads();
        const int* wb = w_sm[kc & 1];

        for (int ct = 0; ct < 12; ++ct) {
            const int co0 = ct * 8;
            int d0 = 0, d1 = 0, d2 = 0, d3 = 0;
            #pragma unroll
            for (int s = 0; s < 3; ++s) {
                int b0 = wb[(co0 + g) * WS + 8 * s + tg];
                int b1 = wb[(co0 + g) * WS + 8 * s + 4 + tg];
                mma_s8(d0, d1, d2, d3, A0[s], A1[s], A2[s], A3[s], b0, b1);
            }
            const int cA = kc * 96 + co0 + 2 * tg, cB = cA + 1;
            const float alA = s_al[cA], bbA = s_bb[cA];
            const float alB = s_al[cB], bbB = s_bb[cB];
            signed char* ob = o_sm + wid * 512 + (ct & 3) * 128;
            ob[(2 * tg) * 16 + g]         = (signed char)requant_sat(d0, alA, bbA, C1);
            ob[(2 * tg + 1) * 16 + g]     = (signed char)requant_sat(d1, alB, bbB, C1);
            ob[(2 * tg) * 16 + g + 8]     = (signed char)requant_sat(d2, alA, bbA, C1);
            ob[(2 * tg + 1) * 16 + g + 8] = (signed char)requant_sat(d3, alB, bbB, C1);

            if ((ct & 3) == 3) {
                __syncwarp();
                int4 v = *(const int4*)(o_sm + wid * 512 + lane * 16);
                int tb = lane >> 3, col = lane & 7;
                int cog = kc * 96 + (ct - 3 + tb) * 8 + col;
                *(int4*)(g_y1 + (size_t)(bw * CMID + cog) * HW_ + hww) = v;
                __syncwarp();
            }
        }
    }
}

// ---------------- k2: depthwise 3x3, writes channel-interleaved g_y2i ----------------
__global__ void __launch_bounds__(256) k2_dw() {
    int t = blockIdx.x * 256 + threadIdx.x;   // grid exact: B_*CMID*28 / 256
    int j = t & 3;
    int Q = t >> 2;
    int h = Q % 28;
    int bcg = Q / 28;
    int cg = bcg % 144;
    int b = bcg / 144;
    int c = 4 * cg + j;
    int base = (b * CMID + c) * HW_;

    int r0[8], r1[8], r2[8];
    const int* p1 = (const int*)(g_y1 + base + h * 28);
    #pragma unroll
    for (int q = 0; q < 7; ++q) r1[q] = p1[q];
    r1[7] = 0;
    if (h > 0) {
        const int* p0 = p1 - 7;
        #pragma unroll
        for (int q = 0; q < 7; ++q) r0[q] = p0[q];
    } else {
        #pragma unroll
        for (int q = 0; q < 7; ++q) r0[q] = 0;
    }
    r0[7] = 0;
    if (h < 27) {
        const int* p2 = p1 + 7;
        #pragma unroll
        for (int q = 0; q < 7; ++q) r2[q] = p2[q];
    } else {
        #pragma unroll
        for (int q = 0; q < 7; ++q) r2[q] = 0;
    }
    r2[7] = 0;

    int wp0 = g_w2p[c * 3 + 0];
    int wp1 = g_w2p[c * 3 + 1];
    int wp2 = g_w2p[c * 3 + 2];
    const float SIXTH = 1.0f / 6.0f;
    float al = (g_s[1] * g_ws2[c]) * SIXTH;
    float bb = g_bf2[c] * SIXTH;
    float C2 = 6.0f / g_s[2];

    int ow[7];
    int qv[4];
    #pragma unroll
    for (int w = 0; w < 28; ++w) {
        int op0, op1, op2;
        if (w == 0) {
            op0 = __byte_perm(r0[0], 0, 0x2104);
            op1 = __byte_perm(r1[0], 0, 0x2104);
            op2 = __byte_perm(r2[0], 0, 0x2104);
        } else {
            int s = w - 1, q = s >> 2, o = s & 3;
            unsigned sel = 0x3210u + (unsigned)o * 0x1111u;
            op0 = __byte_perm(r0[q], r0[q + 1], sel);
            op1 = __byte_perm(r1[q], r1[q + 1], sel);
            op2 = __byte_perm(r2[q], r2[q + 1], sel);
        }
        int acc = __dp4a(op0, wp0, __dp4a(op1, wp1, __dp4a(op2, wp2, 0)));
        qv[w & 3] = requant_sat(acc, al, bb, C2);
        if ((w & 3) == 3) {
            int lo = __byte_perm(qv[0], qv[1], 0x0040);
            int hi = __byte_perm(qv[2], qv[3], 0x0040);
            ow[w >> 2] = __byte_perm(lo, hi, 0x5410);
        }
    }

    // quad transpose -> interleaved words
    int lane = threadIdx.x & 31;
    int qb = lane & ~3;
    int ob = (b * 144 + cg) * HW_ + h * 28;
    unsigned selj = (unsigned)j | ((unsigned)(j + 4) << 4);
    #pragma unroll
    for (int q = 0; q < 7; ++q) {
        int v0 = __shfl_sync(0xFFFFFFFFu, ow[q], qb + 0);
        int v1 = __shfl_sync(0xFFFFFFFFu, ow[q], qb + 1);
        int v2 = __shfl_sync(0xFFFFFFFFu, ow[q], qb + 2);
        int v3 = __shfl_sync(0xFFFFFFFFu, ow[q], qb + 3);
        int s1 = __byte_perm(v0, v1, selj);
        int s2 = __byte_perm(v2, v3, selj);
        g_y2i[ob + 4 * q + j] = __byte_perm(s1, s2, 0x5410);
    }
}

// ---------------- k3: 1x1 conv (576->96) IMMA, cp.async double-buffered ----------------
#define AS3 136
__global__ void __launch_bounds__(256, 3) k3_conv3(const float* __restrict__ x,
                                                   float* __restrict__ out) {
    __shared__ __align__(16) int a_sm[2][24 * AS3];    // 26112 B
    __shared__ __align__(16) int w_sm[2][96 * WS];     // 21504 B
    __shared__ float s_al[96], s_bb[96];

    const int tid = threadIdx.x, lane = tid & 31, wid = tid >> 5;
    const int g = lane >> 2, tg = lane & 3;
    const int n0 = blockIdx.x * 128;
    const int p0 = wid * 16;
    const int nn = n0 + p0;
    const int bw = nn / HW_;
    const int hww = nn - bw * HW_;
    const float s3 = g_s[3], inv_s3 = 1.0f / s3;

    // prologue: chunk 0 (A: 24 cg rows x 128 px; B: 96 co x 24 words)
    for (int idx = tid; idx < 768; idx += 256) {
        int r = idx >> 5, q4 = idx & 31;
        int n = n0 + 4 * q4, b = n / HW_, hw = n - b * HW_;
        CP16(smem_u32(&a_sm[0][r * AS3 + 4 * q4]),
             &g_y2i[(size_t)(b * 144 + r) * HW_ + hw]);
    }
    for (int idx = tid; idx < 576; idx += 256) {
        int co = idx / 6, seg = idx % 6;
        CP16(smem_u32(&w_sm[0][co * WS + 4 * seg]), &g_w3p[co * 144 + 4 * seg]);
    }
    CP_COMMIT();

    if (tid < 96) {
        s_al[tid] = (g_s[2] * g_ws3[tid]) * inv_s3;
        s_bb[tid] = g_bf3[tid] * inv_s3;
    }

    int acc[12][4];
    #pragma unroll
    for (int nt = 0; nt < 12; ++nt)
        #pragma unroll
        for (int q = 0; q < 4; ++q) acc[nt][q] = 0;

    for (int kc = 0; kc < 6; ++kc) {        // 6 K-chunks of 96 channels (24 cgs)
        __syncthreads();                    // done reading buf (kc+1)&1
        if (kc < 5) {
            int nb = (kc + 1) & 1;
            for (int idx = tid; idx < 768; idx += 256) {
                int r = idx >> 5, q4 = idx & 31;
                int n = n0 + 4 * q4, b = n / HW_, hw = n - b * HW_;
                CP16(smem_u32(&a_sm[nb][r * AS3 + 4 * q4]),
                     &g_y2i[(size_t)(b * 144 + (kc + 1) * 24 + r) * HW_ + hw]);
            }
            for (int idx = tid; idx < 576; idx += 256) {
                int co = idx / 6, seg = idx % 6;
                CP16(smem_u32(&w_sm[nb][co * WS + 4 * seg]),
                     &g_w3p[co * 144 + (kc + 1) * 24 + 4 * seg]);
            }
            CP_COMMIT();
            CP_WAIT1();
        } else {
            CP_WAIT0();
        }
        __syncthreads();
        const int* ab = a_sm[kc & 1];
        const int* wb = w_sm[kc & 1];

        #pragma unroll
        for (int s = 0; s < 3; ++s) {
            int a0 = ab[(8 * s + tg) * AS3 + p0 + g];
            int a1 = ab[(8 * s + tg) * AS3 + p0 + g + 8];
            int a2 = ab[(8 * s + 4 + tg) * AS3 + p0 + g];
            int a3 = ab[(8 * s + 4 + tg) * AS3 + p0 + g + 8];
            #pragma unroll
            for (int nt = 0; nt < 12; ++nt) {
                int b0 = wb[(8 * nt + g) * WS + 8 * s + tg];
                int b1 = wb[(8 * nt + g) * WS + 8 * s + 4 + tg];
                mma_s8(acc[nt][0], acc[nt][1], acc[nt][2], acc[nt][3],
                       a0, a1, a2, a3, b0, b1);
            }
        }
    }

    #pragma unroll
    for (int nt = 0; nt < 12; ++nt) {
        const int cA = 8 * nt + 2 * tg, cB = cA + 1;
        const float alA = s_al[cA], bbA = s_bb[cA];
        const float alB = s_al[cB], bbB = s_bb[cB];
        size_t oA = (size_t)(bw * COUT + cA) * HW_ + hww + g;
        size_t oB = (size_t)(bw * COUT + cB) * HW_ + hww + g;
        float t, q;
        t = fmaf((float)acc[nt][0], alA, bbA); t = fmaf(x[oA], inv_s3, t);
        q = rintf(fminf(fmaxf(t, -127.f), 127.f));
        out[oA] = q * s3;
        t = fmaf((float)acc[nt][1], alB, bbB); t = fmaf(x[oB], inv_s3, t);
        q = rintf(fminf(fmaxf(t, -127.f), 127.f));
        out[oB] = q * s3;
        t = fmaf((float)acc[nt][2], alA, bbA); t = fmaf(x[oA + 8], inv_s3, t);
        q = rintf(fminf(fmaxf(t, -127.f), 127.f));
        out[oA + 8] = q * s3;
        t = fmaf((float)acc[nt][3], alB, bbB); t = fmaf(x[oB + 8], inv_s3, t);
        q = rintf(fminf(fmaxf(t, -127.f), 127.f));
        out[oB + 8] = q * s3;
    }
}

// ---------------- launch ----------------
extern "C" void kernel_launch(void* const* d_in, const int* in_sizes, int n_in,
                              void* d_out, int out_size) {
    const float* x  = (const float*)d_in[0];
    const float* w1 = (const float*)d_in[1];
    const float* g1 = (const float*)d_in[2];
    const float* b1 = (const float*)d_in[3];
    const float* m1 = (const float*)d_in[4];
    const float* v1 = (const float*)d_in[5];
    const float* w2 = (const float*)d_in[6];
    const float* g2 = (const float*)d_in[7];
    const float* b2 = (const float*)d_in[8];
    const float* m2 = (const float*)d_in[9];
    const float* v2 = (const float*)d_in[10];
    const float* w3 = (const float*)d_in[11];
    const float* g3 = (const float*)d_in[12];
    const float* b3 = (const float*)d_in[13];
    const float* m3 = (const float*)d_in[14];
    const float* v3 = (const float*)d_in[15];
    const float* r0 = (const float*)d_in[16];
    const float* r1 = (const float*)d_in[17];
    const float* r2 = (const float*)d_in[18];
    const float* r3 = (const float*)d_in[19];
    const int*   cl = (const int*)d_in[20];

    float* out = (float*)d_out;
    const int NOUT = B_ * COUT * HW_;
    float* s3out = (out_size > NOUT) ? out + NOUT : nullptr;

    prep_all<<<156, 256>>>(w1, g1, b1, m1, v1,
                           w2, g2, b2, m2, v2,
                           w3, g3, b3, m3, v3,
                           r0, r1, r2, r3, cl, s3out);
    k1_conv1<<<NPIX / 128, 256>>>(x);
    k2_dw<<<(B_ * CMID * 28) / 256, 256>>>();
    k3_conv3<<<NPIX / 128, 256>>>(x, out);
}

// round 9
// speedup vs baseline: 1.0102x; 1.0102x over previous
#include <cuda_runtime.h>
#include <math.h>
#include <stdint.h>

#define B_    64
#define CIN   96
#define CMID  576
#define COUT  96
#define HW_   784
#define NPIX  (B_*HW_)
#define NBITF 127.0f

__device__ float g_s[4];
__device__ float g_ws1[CMID], g_bf1[CMID];
__device__ float g_ws2[CMID], g_bf2[CMID];
__device__ float g_ws3[COUT], g_bf3[COUT];
__device__ __align__(16) int g_w1p[CMID * 24];    // [co][24 kwords]
__device__ __align__(16) int g_w2p[CMID * 3];
__device__ __align__(16) int g_w3p[COUT * 144];   // [co][144 kwords]
__device__ __align__(16) signed char g_y1[B_ * CMID * HW_];   // channel-major
__device__ __align__(16) int g_y2i[B_ * 144 * HW_];           // interleaved words

// ---------------- cp.async helpers ----------------
__device__ __forceinline__ uint32_t smem_u32(const void* p) {
    uint32_t a;
    asm("{ .reg .u64 t; cvta.to.shared.u64 t, %1; cvt.u32.u64 %0, t; }" : "=r"(a) : "l"(p));
    return a;
}
#define CP16(dst, src) \
    asm volatile("cp.async.cg.shared.global [%0], [%1], 16;" :: "r"(dst), "l"(src))
#define CP_COMMIT() asm volatile("cp.async.commit_group;")
#define CP_WAIT0()  asm volatile("cp.async.wait_group 0;")
#define CP_WAIT1()  asm volatile("cp.async.wait_group 1;")

// ---------------- prep ----------------
__global__ void __launch_bounds__(256) prep_all(
    const float* __restrict__ w1, const float* __restrict__ g1, const float* __restrict__ b1,
    const float* __restrict__ m1, const float* __restrict__ v1,
    const float* __restrict__ w2, const float* __restrict__ g2, const float* __restrict__ b2,
    const float* __restrict__ m2, const float* __restrict__ v2,
    const float* __restrict__ w3, const float* __restrict__ g3, const float* __restrict__ b3,
    const float* __restrict__ m3, const float* __restrict__ v3,
    const float* __restrict__ r0, const float* __restrict__ r1,
    const float* __restrict__ r2, const float* __restrict__ r3,
    const int* __restrict__ cl, float* s3out) {
    __shared__ float sv[8][CMID];
    __shared__ signed char qs[8][CMID];
    const int w = threadIdx.x >> 5, lane = threadIdx.x & 31;
    const int gw = blockIdx.x * 8 + w;

    if (blockIdx.x == 0 && threadIdx.x == 0) {
        int c = cl[0];
        g_s[0] = r0[c] / NBITF;
        g_s[1] = r1[c] / NBITF;
        g_s[2] = r2[c] / NBITF;
        float s3 = r3[c] / NBITF;
        g_s[3] = s3;
        if (s3out) *s3out = s3;
    }

    if (gw < CMID) {
        int co = gw;
        float scale = g1[co] / sqrtf(v1[co] + 1e-5f);
        float m = 0.f;
        for (int k = lane; k < CIN; k += 32) {
            float v = w1[co * CIN + k] * scale;
            sv[w][k] = v;
            m = fmaxf(m, fabsf(v));
        }
        #pragma unroll
        for (int s = 16; s > 0; s >>= 1) m = fmaxf(m, __shfl_xor_sync(0xFFFFFFFF, m, s));
        float sc = m / NBITF;
        if (lane == 0) { g_ws1[co] = sc; g_bf1[co] = b1[co] - m1[co] * scale; }
        for (int k = lane; k < CIN; k += 32) {
            float q = fminf(fmaxf(rintf(sv[w][k] / sc), -127.f), 127.f);
            qs[w][k] = (signed char)q;
        }
        __syncwarp();
        if (lane < 24) {
            const signed char* q = &qs[w][4 * lane];
            g_w1p[co * 24 + lane] = (q[0] & 0xFF) | ((q[1] & 0xFF) << 8) |
                                    ((q[2] & 0xFF) << 16) | ((q[3] & 0xFF) << 24);
        }
    } else if (gw < 2 * CMID) {
        int co = gw - CMID;
        float scale = g2[co] / sqrtf(v2[co] + 1e-5f);
        float m = 0.f;
        if (lane < 9) {
            float v = w2[co * 9 + lane] * scale;
            sv[w][lane] = v;
            m = fabsf(v);
        }
        #pragma unroll
        for (int s = 16; s > 0; s >>= 1) m = fmaxf(m, __shfl_xor_sync(0xFFFFFFFF, m, s));
        float sc = m / NBITF;
        if (lane == 0) { g_ws2[co] = sc; g_bf2[co] = b2[co] - m2[co] * scale; }
        if (lane < 9) {
            float q = fminf(fmaxf(rintf(sv[w][lane] / sc), -127.f), 127.f);
            qs[w][lane] = (signed char)q;
        }
        __syncwarp();
        if (lane < 3) {
            const signed char* q = &qs[w][3 * lane];
            g_w2p[co * 3 + lane] = (q[0] & 0xFF) | ((q[1] & 0xFF) << 8) | ((q[2] & 0xFF) << 16);
        }
    } else {
        int co = gw - 2 * CMID;
        float scale = g3[co] / sqrtf(v3[co] + 1e-5f);
        float m = 0.f;
        for (int k = lane; k < CMID; k += 32) {
            float v = w3[co * CMID + k] * scale;
            sv[w][k] = v;
            m = fmaxf(m, fabsf(v));
        }
        #pragma unroll
        for (int s = 16; s > 0; s >>= 1) m = fmaxf(m, __shfl_xor_sync(0xFFFFFFFF, m, s));
        float sc = m / NBITF;
        if (lane == 0) { g_ws3[co] = sc; g_bf3[co] = b3[co] - m3[co] * scale; }
        for (int k = lane; k < CMID; k += 32) {
            float q = fminf(fmaxf(rintf(sv[w][k] / sc), -127.f), 127.f);
            qs[w][k] = (signed char)q;
        }
        __syncwarp();
        for (int p = lane; p < 144; p += 32) {
            const signed char* q = &qs[w][4 * p];
            g_w3p[co * 144 + p] = (q[0] & 0xFF) | ((q[1] & 0xFF) << 8) |
                                  ((q[2] & 0xFF) << 16) | ((q[3] & 0xFF) << 24);
        }
    }
}

// ---------------- IMMA + requant ----------------
__device__ __forceinline__ void mma_s8(int& d0, int& d1, int& d2, int& d3,
                                       int a0, int a1, int a2, int a3,
                                       int b0, int b1) {
    asm volatile(
        "mma.sync.aligned.m16n8k32.row.col.s32.s8.s8.s32 "
        "{%0,%1,%2,%3}, {%4,%5,%6,%7}, {%8,%9}, {%0,%1,%2,%3};"
        : "+r"(d0), "+r"(d1), "+r"(d2), "+r"(d3)
        : "r"(a0), "r"(a1), "r"(a2), "r"(a3), "r"(b0), "r"(b1));
}
__device__ __forceinline__ int requant_sat(int acc, float al6, float bb6, float C) {
    float z = __saturatef(fmaf((float)acc, al6, bb6));
    int q = __float2int_rn(z * C);
    return q > 127 ? 127 : q;
}

// ---------------- k1: quant(x) + 1x1 conv (96->576) IMMA, pipelined weights ----------------
#define AS1 136
#define WS  28
__global__ void __launch_bounds__(256, 3) k1_conv1(const float* __restrict__ x) {
    __shared__ __align__(16) int a_sm[24 * AS1];
    __shared__ __align__(16) int w_sm[2][96 * WS];
    __shared__ float s_al[CMID], s_bb[CMID];
    __shared__ __align__(16) signed char o_sm[8 * 512];

    const int tid = threadIdx.x;
    const int n0 = blockIdx.x * 128;
    const float s0 = g_s[0];
    const float inv_s0 = 1.0f / s0;
    const float C1 = 6.0f / g_s[1];
    const float SIXTH = 1.0f / 6.0f;

    for (int idx = tid; idx < 576; idx += 256) {
        int co = idx / 6, seg = idx % 6;
        CP16(smem_u32(&w_sm[0][co * WS + 4 * seg]), &g_w1p[co * 24 + 4 * seg]);
    }
    CP_COMMIT();

    for (int i = tid; i < CMID; i += 256) {
        s_al[i] = (s0 * g_ws1[i]) * SIXTH;
        s_bb[i] = g_bf1[i] * SIXTH;
    }

    for (int idx = tid; idx < 768; idx += 256) {
        int cg = idx >> 5, q4 = idx & 31;
        int n = n0 + 4 * q4;
        int b = n / HW_;
        int hw = n - b * HW_;
        int q[4][4];
        #pragma unroll
        for (int j = 0; j < 4; ++j) {
            float4 v = *(const float4*)(x + ((size_t)(b * CIN + 4 * cg + j) * HW_ + hw));
            float f;
            f = fminf(fmaxf(rintf(v.x * inv_s0), -127.f), 127.f); q[j][0] = (int)f;
            f = fminf(fmaxf(rintf(v.y * inv_s0), -127.f), 127.f); q[j][1] = (int)f;
            f = fminf(fmaxf(rintf(v.z * inv_s0), -127.f), 127.f); q[j][2] = (int)f;
            f = fminf(fmaxf(rintf(v.w * inv_s0), -127.f), 127.f); q[j][3] = (int)f;
        }
        int w[4];
        #pragma unroll
        for (int p = 0; p < 4; ++p) {
            int lo = __byte_perm(q[0][p], q[1][p], 0x0040);
            int hi = __byte_perm(q[2][p], q[3][p], 0x0040);
            w[p] = __byte_perm(lo, hi, 0x5410);
        }
        *(int4*)&a_sm[cg * AS1 + 4 * q4] = make_int4(w[0], w[1], w[2], w[3]);
    }

    const int lane = tid & 31, wid = tid >> 5;
    const int g = lane >> 2, tg = lane & 3;
    const int p0 = wid * 16;
    const int nn = n0 + p0;
    const int bw = nn / HW_;
    const int hww = nn - bw * HW_;

    __syncthreads();

    int A0[3], A1[3], A2[3], A3[3];
    #pragma unroll
    for (int s = 0; s < 3; ++s) {
        A0[s] = a_sm[(8 * s + tg) * AS1 + p0 + g];
        A1[s] = a_sm[(8 * s + tg) * AS1 + p0 + g + 8];
        A2[s] = a_sm[(8 * s + 4 + tg) * AS1 + p0 + g];
        A3[s] = a_sm[(8 * s + 4 + tg) * AS1 + p0 + g + 8];
    }

    for (int kc = 0; kc < 6; ++kc) {
        __syncthreads();
        if (kc < 5) {
            for (int idx = tid; idx < 576; idx += 256) {
                int co = idx / 6, seg = idx % 6;
                CP16(smem_u32(&w_sm[(kc + 1) & 1][co * WS + 4 * seg]),
                     &g_w1p[((kc + 1) * 96 + co) * 24 + 4 * seg]);
            }
            CP_COMMIT();
            CP_WAIT1();
        } else {
            CP_WAIT0();
        }
        __syncthreads();
        const int* wb = w_sm[kc & 1];

        for (int ct = 0; ct < 12; ++ct) {
            const int co0 = ct * 8;
            int d0 = 0, d1 = 0, d2 = 0, d3 = 0;
            #pragma unroll
            for (int s = 0; s < 3; ++s) {
                int b0 = wb[(co0 + g) * WS + 8 * s + tg];
                int b1 = wb[(co0 + g) * WS + 8 * s + 4 + tg];
                mma_s8(d0, d1, d2, d3, A0[s], A1[s], A2[s], A3[s], b0, b1);
            }
            const int cA = kc * 96 + co0 + 2 * tg, cB = cA + 1;
            const float alA = s_al[cA], bbA = s_bb[cA];
            const float alB = s_al[cB], bbB = s_bb[cB];
            signed char* ob = o_sm + wid * 512 + (ct & 3) * 128;
            ob[(2 * tg) * 16 + g]         = (signed char)requant_sat(d0, alA, bbA, C1);
            ob[(2 * tg + 1) * 16 + g]     = (signed char)requant_sat(d1, alB, bbB, C1);
            ob[(2 * tg) * 16 + g + 8]     = (signed char)requant_sat(d2, alA, bbA, C1);
            ob[(2 * tg + 1) * 16 + g + 8] = (signed char)requant_sat(d3, alB, bbB, C1);

            if ((ct & 3) == 3) {
                __syncwarp();
                int4 v = *(const int4*)(o_sm + wid * 512 + lane * 16);
                int tb = lane >> 3, col = lane & 7;
                int cog = kc * 96 + (ct - 3 + tb) * 8 + col;
                *(int4*)(g_y1 + (size_t)(bw * CMID + cog) * HW_ + hww) = v;
                __syncwarp();
            }
        }
    }
}

// ---------------- k2: depthwise 3x3 -> interleaved g_y2i ----------------
__global__ void __launch_bounds__(256) k2_dw() {
    int t = blockIdx.x * 256 + threadIdx.x;
    int j = t & 3;
    int Q = t >> 2;
    int h = Q % 28;
    int bcg = Q / 28;
    int cg = bcg % 144;
    int b = bcg / 144;
    int c = 4 * cg + j;
    int base = (b * CMID + c) * HW_;

    int r0[8], r1[8], r2[8];
    const int* p1 = (const int*)(g_y1 + base + h * 28);
    #pragma unroll
    for (int q = 0; q < 7; ++q) r1[q] = p1[q];
    r1[7] = 0;
    if (h > 0) {
        const int* p0 = p1 - 7;
        #pragma unroll
        for (int q = 0; q < 7; ++q) r0[q] = p0[q];
    } else {
        #pragma unroll
        for (int q = 0; q < 7; ++q) r0[q] = 0;
    }
    r0[7] = 0;
    if (h < 27) {
        const int* p2 = p1 + 7;
        #pragma unroll
        for (int q = 0; q < 7; ++q) r2[q] = p2[q];
    } else {
        #pragma unroll
        for (int q = 0; q < 7; ++q) r2[q] = 0;
    }
    r2[7] = 0;

    int wp0 = g_w2p[c * 3 + 0];
    int wp1 = g_w2p[c * 3 + 1];
    int wp2 = g_w2p[c * 3 + 2];
    const float SIXTH = 1.0f / 6.0f;
    float al = (g_s[1] * g_ws2[c]) * SIXTH;
    float bb = g_bf2[c] * SIXTH;
    float C2 = 6.0f / g_s[2];

    int ow[7];
    int qv[4];
    #pragma unroll
    for (int w = 0; w < 28; ++w) {
        int op0, op1, op2;
        if (w == 0) {
            op0 = __byte_perm(r0[0], 0, 0x2104);
            op1 = __byte_perm(r1[0], 0, 0x2104);
            op2 = __byte_perm(r2[0], 0, 0x2104);
        } else {
            int s = w - 1, q = s >> 2, o = s & 3;
            unsigned sel = 0x3210u + (unsigned)o * 0x1111u;
            op0 = __byte_perm(r0[q], r0[q + 1], sel);
            op1 = __byte_perm(r1[q], r1[q + 1], sel);
            op2 = __byte_perm(r2[q], r2[q + 1], sel);
        }
        int acc = __dp4a(op0, wp0, __dp4a(op1, wp1, __dp4a(op2, wp2, 0)));
        qv[w & 3] = requant_sat(acc, al, bb, C2);
        if ((w & 3) == 3) {
            int lo = __byte_perm(qv[0], qv[1], 0x0040);
            int hi = __byte_perm(qv[2], qv[3], 0x0040);
            ow[w >> 2] = __byte_perm(lo, hi, 0x5410);
        }
    }

    int lane = threadIdx.x & 31;
    int qb = lane & ~3;
    int ob = (b * 144 + cg) * HW_ + h * 28;
    unsigned selj = (unsigned)j | ((unsigned)(j + 4) << 4);
    #pragma unroll
    for (int q = 0; q < 7; ++q) {
        int v0 = __shfl_sync(0xFFFFFFFFu, ow[q], qb + 0);
        int v1 = __shfl_sync(0xFFFFFFFFu, ow[q], qb + 1);
        int v2 = __shfl_sync(0xFFFFFFFFu, ow[q], qb + 2);
        int v3 = __shfl_sync(0xFFFFFFFFu, ow[q], qb + 3);
        int s1 = __byte_perm(v0, v1, selj);
        int s2 = __byte_perm(v2, v3, selj);
        g_y2i[ob + 4 * q + j] = __byte_perm(s1, s2, 0x5410);
    }
}

// ---------------- k3: 1x1 conv (576->96) IMMA + coalesced staged epilogue ----------------
#define AS3 136
#define STG_STRIDE 132
__global__ void __launch_bounds__(256, 3) k3_conv3(const float* __restrict__ x,
                                                   float* __restrict__ out) {
    __shared__ union {
        struct {
            int a[2][24 * AS3];   // 26112 B
            int w[2][96 * WS];    // 21504 B
        } pipe;
        int stage[48 * STG_STRIDE];  // 25344 B (epilogue reuse)
    } sm;
    __shared__ float s_al[96], s_bb[96];

    const int tid = threadIdx.x, lane = tid & 31, wid = tid >> 5;
    const int g = lane >> 2, tg = lane & 3;
    const int n0 = blockIdx.x * 128;
    const int p0 = wid * 16;
    const float s3 = g_s[3], inv_s3 = 1.0f / s3;

    // prologue: chunk 0
    for (int idx = tid; idx < 768; idx += 256) {
        int r = idx >> 5, q4 = idx & 31;
        int n = n0 + 4 * q4, b = n / HW_, hw = n - b * HW_;
        CP16(smem_u32(&sm.pipe.a[0][r * AS3 + 4 * q4]),
             &g_y2i[(size_t)(b * 144 + r) * HW_ + hw]);
    }
    for (int idx = tid; idx < 576; idx += 256) {
        int co = idx / 6, seg = idx % 6;
        CP16(smem_u32(&sm.pipe.w[0][co * WS + 4 * seg]), &g_w3p[co * 144 + 4 * seg]);
    }
    CP_COMMIT();

    if (tid < 96) {
        s_al[tid] = (g_s[2] * g_ws3[tid]) * inv_s3;
        s_bb[tid] = g_bf3[tid] * inv_s3;
    }

    int acc[12][4];
    #pragma unroll
    for (int nt = 0; nt < 12; ++nt)
        #pragma unroll
        for (int q = 0; q < 4; ++q) acc[nt][q] = 0;

    for (int kc = 0; kc < 6; ++kc) {
        __syncthreads();
        if (kc < 5) {
            int nb = (kc + 1) & 1;
            for (int idx = tid; idx < 768; idx += 256) {
                int r = idx >> 5, q4 = idx & 31;
                int n = n0 + 4 * q4, b = n / HW_, hw = n - b * HW_;
                CP16(smem_u32(&sm.pipe.a[nb][r * AS3 + 4 * q4]),
                     &g_y2i[(size_t)(b * 144 + (kc + 1) * 24 + r) * HW_ + hw]);
            }
            for (int idx = tid; idx < 576; idx += 256) {
                int co = idx / 6, seg = idx % 6;
                CP16(smem_u32(&sm.pipe.w[nb][co * WS + 4 * seg]),
                     &g_w3p[co * 144 + (kc + 1) * 24 + 4 * seg]);
            }
            CP_COMMIT();
            CP_WAIT1();
        } else {
            CP_WAIT0();
        }
        __syncthreads();
        const int* ab = sm.pipe.a[kc & 1];
        const int* wb = sm.pipe.w[kc & 1];

        #pragma unroll
        for (int s = 0; s < 3; ++s) {
            int a0 = ab[(8 * s + tg) * AS3 + p0 + g];
            int a1 = ab[(8 * s + tg) * AS3 + p0 + g + 8];
            int a2 = ab[(8 * s + 4 + tg) * AS3 + p0 + g];
            int a3 = ab[(8 * s + 4 + tg) * AS3 + p0 + g + 8];
            #pragma unroll
            for (int nt = 0; nt < 12; ++nt) {
                int b0 = wb[(8 * nt + g) * WS + 8 * s + tg];
                int b1 = wb[(8 * nt + g) * WS + 8 * s + 4 + tg];
                mma_s8(acc[nt][0], acc[nt][1], acc[nt][2], acc[nt][3],
                       a0, a1, a2, a3, b0, b1);
            }
        }
    }

    // ---- staged, coalesced epilogue: 2 rounds of 48 channels ----
    #pragma unroll
    for (int r = 0; r < 2; ++r) {
        __syncthreads();   // round 0: main loop done; round 1: writers done reading stage
        #pragma unroll
        for (int i = 0; i < 6; ++i) {
            int nt = 6 * r + i;
            int cl0 = 8 * i + 2 * tg;          // local channel in [0,48)
            sm.stage[cl0 * STG_STRIDE + p0 + g]           = acc[nt][0];
            sm.stage[(cl0 + 1) * STG_STRIDE + p0 + g]     = acc[nt][1];
            sm.stage[cl0 * STG_STRIDE + p0 + g + 8]       = acc[nt][2];
            sm.stage[(cl0 + 1) * STG_STRIDE + p0 + g + 8] = acc[nt][3];
        }
        __syncthreads();
        // writer: warp wid owns local channels 6*wid .. 6*wid+5, lane covers px 4*lane..+3
        int n = n0 + 4 * lane;
        int b = n / HW_;
        int hw = n - b * HW_;
        #pragma unroll
        for (int i = 0; i < 6; ++i) {
            int cl = 6 * wid + i;
            int c = 48 * r + cl;
            const int4 v = *(const int4*)&sm.stage[cl * STG_STRIDE + 4 * lane];
            const float al = s_al[c], bb = s_bb[c];
            size_t off = (size_t)(b * COUT + c) * HW_ + hw;
            float4 xv = *(const float4*)(x + off);
            float t0, q0, t1, q1, t2, q2, t3, q3;
            t0 = fmaf((float)v.x, al, bb); t0 = fmaf(xv.x, inv_s3, t0);
            q0 = rintf(fminf(fmaxf(t0, -127.f), 127.f));
            t1 = fmaf((float)v.y, al, bb); t1 = fmaf(xv.y, inv_s3, t1);
            q1 = rintf(fminf(fmaxf(t1, -127.f), 127.f));
            t2 = fmaf((float)v.z, al, bb); t2 = fmaf(xv.z, inv_s3, t2);
            q2 = rintf(fminf(fmaxf(t2, -127.f), 127.f));
            t3 = fmaf((float)v.w, al, bb); t3 = fmaf(xv.w, inv_s3, t3);
            q3 = rintf(fminf(fmaxf(t3, -127.f), 127.f));
            *(float4*)(out + off) = make_float4(q0 * s3, q1 * s3, q2 * s3, q3 * s3);
        }
    }
}

// ---------------- launch ----------------
extern "C" void kernel_launch(void* const* d_in, const int* in_sizes, int n_in,
                              void* d_out, int out_size) {
    const float* x  = (const float*)d_in[0];
    const float* w1 = (const float*)d_in[1];
    const float* g1 = (const float*)d_in[2];
    const float* b1 = (const float*)d_in[3];
    const float* m1 = (const float*)d_in[4];
    const float* v1 = (const float*)d_in[5];
    const float* w2 = (const float*)d_in[6];
    const float* g2 = (const float*)d_in[7];
    const float* b2 = (const float*)d_in[8];
    const float* m2 = (const float*)d_in[9];
    const float* v2 = (const float*)d_in[10];
    const float* w3 = (const float*)d_in[11];
    const float* g3 = (const float*)d_in[12];
    const float* b3 = (const float*)d_in[13];
    const float* m3 = (const float*)d_in[14];
    const float* v3 = (const float*)d_in[15];
    const float* r0 = (const float*)d_in[16];
    const float* r1 = (const float*)d_in[17];
    const float* r2 = (const float*)d_in[18];
    const float* r3 = (const float*)d_in[19];
    const int*   cl = (const int*)d_in[20];

    float* out = (float*)d_out;
    const int NOUT = B_ * COUT * HW_;
    float* s3out = (out_size > NOUT) ? out + NOUT : nullptr;

    prep_all<<<156, 256>>>(w1, g1, b1, m1, v1,
                           w2, g2, b2, m2, v2,
                           w3, g3, b3, m3, v3,
                           r0, r1, r2, r3, cl, s3out);
    k1_conv1<<<NPIX / 128, 256>>>(x);
    k2_dw<<<(B_ * CMID * 28) / 256, 256>>>();
    k3_conv3<<<NPIX / 128, 256>>>(x, out);
}

// round 10
// speedup vs baseline: 1.0190x; 1.0087x over previous
#include <cuda_runtime.h>
#include <math.h>
#include <stdint.h>

#define B_    64
#define CIN   96
#define CMID  576
#define COUT  96
#define HW_   784
#define NPIX  (B_*HW_)
#define NBITF 127.0f

__device__ float g_s[4];
__device__ float g_ws1[CMID], g_bf1[CMID];
__device__ float g_ws2[CMID], g_bf2[CMID];
__device__ float g_ws3[COUT], g_bf3[COUT];
__device__ __align__(16) int g_w1p[CMID * 24];    // [co][24 kwords]
__device__ __align__(16) int g_w2p[CMID * 3];
__device__ __align__(16) int g_w3p[COUT * 144];   // [co][144 kwords]
__device__ __align__(16) signed char g_y1[B_ * CMID * HW_];   // channel-major
__device__ __align__(16) int g_y2i[B_ * 144 * HW_];           // interleaved words

// ---------------- cp.async helpers ----------------
__device__ __forceinline__ uint32_t smem_u32(const void* p) {
    uint32_t a;
    asm("{ .reg .u64 t; cvta.to.shared.u64 t, %1; cvt.u32.u64 %0, t; }" : "=r"(a) : "l"(p));
    return a;
}
#define CP16(dst, src) \
    asm volatile("cp.async.cg.shared.global [%0], [%1], 16;" :: "r"(dst), "l"(src))
#define CP_COMMIT() asm volatile("cp.async.commit_group;")
#define CP_WAIT0()  asm volatile("cp.async.wait_group 0;")
#define CP_WAIT1()  asm volatile("cp.async.wait_group 1;")

// ---------------- prep ----------------
__global__ void __launch_bounds__(256) prep_all(
    const float* __restrict__ w1, const float* __restrict__ g1, const float* __restrict__ b1,
    const float* __restrict__ m1, const float* __restrict__ v1,
    const float* __restrict__ w2, const float* __restrict__ g2, const float* __restrict__ b2,
    const float* __restrict__ m2, const float* __restrict__ v2,
    const float* __restrict__ w3, const float* __restrict__ g3, const float* __restrict__ b3,
    const float* __restrict__ m3, const float* __restrict__ v3,
    const float* __restrict__ r0, const float* __restrict__ r1,
    const float* __restrict__ r2, const float* __restrict__ r3,
    const int* __restrict__ cl, float* s3out) {
    __shared__ float sv[8][CMID];
    __shared__ signed char qs[8][CMID];
    const int w = threadIdx.x >> 5, lane = threadIdx.x & 31;
    const int gw = blockIdx.x * 8 + w;

    if (blockIdx.x == 0 && threadIdx.x == 0) {
        int c = cl[0];
        g_s[0] = r0[c] / NBITF;
        g_s[1] = r1[c] / NBITF;
        g_s[2] = r2[c] / NBITF;
        float s3 = r3[c] / NBITF;
        g_s[3] = s3;
        if (s3out) *s3out = s3;
    }

    if (gw < CMID) {
        int co = gw;
        float scale = g1[co] / sqrtf(v1[co] + 1e-5f);
        float m = 0.f;
        for (int k = lane; k < CIN; k += 32) {
            float v = w1[co * CIN + k] * scale;
            sv[w][k] = v;
            m = fmaxf(m, fabsf(v));
        }
        #pragma unroll
        for (int s = 16; s > 0; s >>= 1) m = fmaxf(m, __shfl_xor_sync(0xFFFFFFFF, m, s));
        float sc = m / NBITF;
        if (lane == 0) { g_ws1[co] = sc; g_bf1[co] = b1[co] - m1[co] * scale; }
        for (int k = lane; k < CIN; k += 32) {
            float q = fminf(fmaxf(rintf(sv[w][k] / sc), -127.f), 127.f);
            qs[w][k] = (signed char)q;
        }
        __syncwarp();
        if (lane < 24) {
            const signed char* q = &qs[w][4 * lane];
            g_w1p[co * 24 + lane] = (q[0] & 0xFF) | ((q[1] & 0xFF) << 8) |
                                    ((q[2] & 0xFF) << 16) | ((q[3] & 0xFF) << 24);
        }
    } else if (gw < 2 * CMID) {
        int co = gw - CMID;
        float scale = g2[co] / sqrtf(v2[co] + 1e-5f);
        float m = 0.f;
        if (lane < 9) {
            float v = w2[co * 9 + lane] * scale;
            sv[w][lane] = v;
            m = fabsf(v);
        }
        #pragma unroll
        for (int s = 16; s > 0; s >>= 1) m = fmaxf(m, __shfl_xor_sync(0xFFFFFFFF, m, s));
        float sc = m / NBITF;
        if (lane == 0) { g_ws2[co] = sc; g_bf2[co] = b2[co] - m2[co] * scale; }
        if (lane < 9) {
            float q = fminf(fmaxf(rintf(sv[w][lane] / sc), -127.f), 127.f);
            qs[w][lane] = (signed char)q;
        }
        __syncwarp();
        if (lane < 3) {
            const signed char* q = &qs[w][3 * lane];
            g_w2p[co * 3 + lane] = (q[0] & 0xFF) | ((q[1] & 0xFF) << 8) | ((q[2] & 0xFF) << 16);
        }
    } else {
        int co = gw - 2 * CMID;
        float scale = g3[co] / sqrtf(v3[co] + 1e-5f);
        float m = 0.f;
        for (int k = lane; k < CMID; k += 32) {
            float v = w3[co * CMID + k] * scale;
            sv[w][k] = v;
            m = fmaxf(m, fabsf(v));
        }
        #pragma unroll
        for (int s = 16; s > 0; s >>= 1) m = fmaxf(m, __shfl_xor_sync(0xFFFFFFFF, m, s));
        float sc = m / NBITF;
        if (lane == 0) { g_ws3[co] = sc; g_bf3[co] = b3[co] - m3[co] * scale; }
        for (int k = lane; k < CMID; k += 32) {
            float q = fminf(fmaxf(rintf(sv[w][k] / sc), -127.f), 127.f);
            qs[w][k] = (signed char)q;
        }
        __syncwarp();
        for (int p = lane; p < 144; p += 32) {
            const signed char* q = &qs[w][4 * p];
            g_w3p[co * 144 + p] = (q[0] & 0xFF) | ((q[1] & 0xFF) << 8) |
                                  ((q[2] & 0xFF) << 16) | ((q[3] & 0xFF) << 24);
        }
    }
}

// ---------------- IMMA + requant ----------------
__device__ __forceinline__ void mma_s8(int& d0, int& d1, int& d2, int& d3,
                                       int a0, int a1, int a2, int a3,
                                       int b0, int b1) {
    asm volatile(
        "mma.sync.aligned.m16n8k32.row.col.s32.s8.s8.s32 "
        "{%0,%1,%2,%3}, {%4,%5,%6,%7}, {%8,%9}, {%0,%1,%2,%3};"
        : "+r"(d0), "+r"(d1), "+r"(d2), "+r"(d3)
        : "r"(a0), "r"(a1), "r"(a2), "r"(a3), "r"(b0), "r"(b1));
}
__device__ __forceinline__ int requant_sat(int acc, float al6, float bb6, float C) {
    float z = __saturatef(fmaf((float)acc, al6, bb6));
    int q = __float2int_rn(z * C);
    return q > 127 ? 127 : q;
}

// ---------------- k1: quant(x) + 1x1 conv (96->576) IMMA, pipelined weights ----------------
#define AS1 136
#define WS  28
__global__ void __launch_bounds__(256, 3) k1_conv1(const float* __restrict__ x) {
    __shared__ __align__(16) int a_sm[24 * AS1];
    __shared__ __align__(16) int w_sm[2][96 * WS];
    __shared__ float s_al[CMID], s_bb[CMID];
    __shared__ __align__(16) signed char o_sm[8 * 512];

    const int tid = threadIdx.x;
    const int n0 = blockIdx.x * 128;
    const float s0 = g_s[0];
    const float inv_s0 = 1.0f / s0;
    const float C1 = 6.0f / g_s[1];
    const float SIXTH = 1.0f / 6.0f;

    for (int idx = tid; idx < 576; idx += 256) {
        int co = idx / 6, seg = idx % 6;
        CP16(smem_u32(&w_sm[0][co * WS + 4 * seg]), &g_w1p[co * 24 + 4 * seg]);
    }
    CP_COMMIT();

    for (int i = tid; i < CMID; i += 256) {
        s_al[i] = (s0 * g_ws1[i]) * SIXTH;
        s_bb[i] = g_bf1[i] * SIXTH;
    }

    for (int idx = tid; idx < 768; idx += 256) {
        int cg = idx >> 5, q4 = idx & 31;
        int n = n0 + 4 * q4;
        int b = n / HW_;
        int hw = n - b * HW_;
        int q[4][4];
        #pragma unroll
        for (int j = 0; j < 4; ++j) {
            float4 v = *(const float4*)(x + ((size_t)(b * CIN + 4 * cg + j) * HW_ + hw));
            float f;
            f = fminf(fmaxf(rintf(v.x * inv_s0), -127.f), 127.f); q[j][0] = (int)f;
            f = fminf(fmaxf(rintf(v.y * inv_s0), -127.f), 127.f); q[j][1] = (int)f;
            f = fminf(fmaxf(rintf(v.z * inv_s0), -127.f), 127.f); q[j][2] = (int)f;
            f = fminf(fmaxf(rintf(v.w * inv_s0), -127.f), 127.f); q[j][3] = (int)f;
        }
        int w[4];
        #pragma unroll
        for (int p = 0; p < 4; ++p) {
            int lo = __byte_perm(q[0][p], q[1][p], 0x0040);
            int hi = __byte_perm(q[2][p], q[3][p], 0x0040);
            w[p] = __byte_perm(lo, hi, 0x5410);
        }
        *(int4*)&a_sm[cg * AS1 + 4 * q4] = make_int4(w[0], w[1], w[2], w[3]);
    }

    const int lane = tid & 31, wid = tid >> 5;
    const int g = lane >> 2, tg = lane & 3;
    const int p0 = wid * 16;
    const int nn = n0 + p0;
    const int bw = nn / HW_;
    const int hww = nn - bw * HW_;

    __syncthreads();

    int A0[3], A1[3], A2[3], A3[3];
    #pragma unroll
    for (int s = 0; s < 3; ++s) {
        A0[s] = a_sm[(8 * s + tg) * AS1 + p0 + g];
        A1[s] = a_sm[(8 * s + tg) * AS1 + p0 + g + 8];
        A2[s] = a_sm[(8 * s + 4 + tg) * AS1 + p0 + g];
        A3[s] = a_sm[(8 * s + 4 + tg) * AS1 + p0 + g + 8];
    }

    for (int kc = 0; kc < 6; ++kc) {
        __syncthreads();
        if (kc < 5) {
            for (int idx = tid; idx < 576; idx += 256) {
                int co = idx / 6, seg = idx % 6;
                CP16(smem_u32(&w_sm[(kc + 1) & 1][co * WS + 4 * seg]),
                     &g_w1p[((kc + 1) * 96 + co) * 24 + 4 * seg]);
            }
            CP_COMMIT();
            CP_WAIT1();
        } else {
            CP_WAIT0();
        }
        __syncthreads();
        const int* wb = w_sm[kc & 1];

        for (int ct = 0; ct < 12; ++ct) {
            const int co0 = ct * 8;
            int d0 = 0, d1 = 0, d2 = 0, d3 = 0;
            #pragma unroll
            for (int s = 0; s < 3; ++s) {
                int b0 = wb[(co0 + g) * WS + 8 * s + tg];
                int b1 = wb[(co0 + g) * WS + 8 * s + 4 + tg];
                mma_s8(d0, d1, d2, d3, A0[s], A1[s], A2[s], A3[s], b0, b1);
            }
            const int cA = kc * 96 + co0 + 2 * tg, cB = cA + 1;
            const float alA = s_al[cA], bbA = s_bb[cA];
            const float alB = s_al[cB], bbB = s_bb[cB];
            signed char* ob = o_sm + wid * 512 + (ct & 3) * 128;
            ob[(2 * tg) * 16 + g]         = (signed char)requant_sat(d0, alA, bbA, C1);
            ob[(2 * tg + 1) * 16 + g]     = (signed char)requant_sat(d1, alB, bbB, C1);
            ob[(2 * tg) * 16 + g + 8]     = (signed char)requant_sat(d2, alA, bbA, C1);
            ob[(2 * tg + 1) * 16 + g + 8] = (signed char)requant_sat(d3, alB, bbB, C1);

            if ((ct & 3) == 3) {
                __syncwarp();
                int4 v = *(const int4*)(o_sm + wid * 512 + lane * 16);
                int tb = lane >> 3, col = lane & 7;
                int cog = kc * 96 + (ct - 3 + tb) * 8 + col;
                *(int4*)(g_y1 + (size_t)(bw * CMID + cog) * HW_ + hww) = v;
                __syncwarp();
            }
        }
    }
}

// ---------------- k2: depthwise 3x3 -> interleaved g_y2i ----------------
__global__ void __launch_bounds__(256) k2_dw() {
    int t = blockIdx.x * 256 + threadIdx.x;
    int j = t & 3;
    int Q = t >> 2;
    int h = Q % 28;
    int bcg = Q / 28;
    int cg = bcg % 144;
    int b = bcg / 144;
    int c = 4 * cg + j;
    int base = (b * CMID + c) * HW_;

    int r0[8], r1[8], r2[8];
    const int* p1 = (const int*)(g_y1 + base + h * 28);
    #pragma unroll
    for (int q = 0; q < 7; ++q) r1[q] = p1[q];
    r1[7] = 0;
    if (h > 0) {
        const int* p0 = p1 - 7;
        #pragma unroll
        for (int q = 0; q < 7; ++q) r0[q] = p0[q];
    } else {
        #pragma unroll
        for (int q = 0; q < 7; ++q) r0[q] = 0;
    }
    r0[7] = 0;
    if (h < 27) {
        const int* p2 = p1 + 7;
        #pragma unroll
        for (int q = 0; q < 7; ++q) r2[q] = p2[q];
    } else {
        #pragma unroll
        for (int q = 0; q < 7; ++q) r2[q] = 0;
    }
    r2[7] = 0;

    int wp0 = g_w2p[c * 3 + 0];
    int wp1 = g_w2p[c * 3 + 1];
    int wp2 = g_w2p[c * 3 + 2];
    const float SIXTH = 1.0f / 6.0f;
    float al = (g_s[1] * g_ws2[c]) * SIXTH;
    float bb = g_bf2[c] * SIXTH;
    float C2 = 6.0f / g_s[2];

    int ow[7];
    int qv[4];
    #pragma unroll
    for (int w = 0; w < 28; ++w) {
        int op0, op1, op2;
        if (w == 0) {
            op0 = __byte_perm(r0[0], 0, 0x2104);
            op1 = __byte_perm(r1[0], 0, 0x2104);
            op2 = __byte_perm(r2[0], 0, 0x2104);
        } else {
            int s = w - 1, q = s >> 2, o = s & 3;
            unsigned sel = 0x3210u + (unsigned)o * 0x1111u;
            op0 = __byte_perm(r0[q], r0[q + 1], sel);
            op1 = __byte_perm(r1[q], r1[q + 1], sel);
            op2 = __byte_perm(r2[q], r2[q + 1], sel);
        }
        int acc = __dp4a(op0, wp0, __dp4a(op1, wp1, __dp4a(op2, wp2, 0)));
        qv[w & 3] = requant_sat(acc, al, bb, C2);
        if ((w & 3) == 3) {
            int lo = __byte_perm(qv[0], qv[1], 0x0040);
            int hi = __byte_perm(qv[2], qv[3], 0x0040);
            ow[w >> 2] = __byte_perm(lo, hi, 0x5410);
        }
    }

    int lane = threadIdx.x & 31;
    int qb = lane & ~3;
    int ob = (b * 144 + cg) * HW_ + h * 28;
    unsigned selj = (unsigned)j | ((unsigned)(j + 4) << 4);
    #pragma unroll
    for (int q = 0; q < 7; ++q) {
        int v0 = __shfl_sync(0xFFFFFFFFu, ow[q], qb + 0);
        int v1 = __shfl_sync(0xFFFFFFFFu, ow[q], qb + 1);
        int v2 = __shfl_sync(0xFFFFFFFFu, ow[q], qb + 2);
        int v3 = __shfl_sync(0xFFFFFFFFu, ow[q], qb + 3);
        int s1 = __byte_perm(v0, v1, selj);
        int s2 = __byte_perm(v2, v3, selj);
        g_y2i[ob + 4 * q + j] = __byte_perm(s1, s2, 0x5410);
    }
}

// ---------------- k3: 1x1 conv (576->96) IMMA + coalesced staged epilogue ----------------
#define AS3 136
#define STG_STRIDE 132
__global__ void __launch_bounds__(256, 3) k3_conv3(const float* __restrict__ x,
                                                   float* __restrict__ out) {
    __shared__ union {
        struct {
            int a[2][24 * AS3];   // 26112 B
            int w[2][96 * WS];    // 21504 B
        } pipe;
        int stage[48 * STG_STRIDE];  // 25344 B (epilogue reuse)
    } sm;
    __shared__ float s_al[96], s_bb[96];

    const int tid = threadIdx.x, lane = tid & 31, wid = tid >> 5;
    const int g = lane >> 2, tg = lane & 3;
    const int n0 = blockIdx.x * 128;
    const int p0 = wid * 16;
    const float s3 = g_s[3], inv_s3 = 1.0f / s3;

    // prologue: chunk 0
    for (int idx = tid; idx < 768; idx += 256) {
        int r = idx >> 5, q4 = idx & 31;
        int n = n0 + 4 * q4, b = n / HW_, hw = n - b * HW_;
        CP16(smem_u32(&sm.pipe.a[0][r * AS3 + 4 * q4]),
             &g_y2i[(size_t)(b * 144 + r) * HW_ + hw]);
    }
    for (int idx = tid; idx < 576; idx += 256) {
        int co = idx / 6, seg = idx % 6;
        CP16(smem_u32(&sm.pipe.w[0][co * WS + 4 * seg]), &g_w3p[co * 144 + 4 * seg]);
    }
    CP_COMMIT();

    if (tid < 96) {
        s_al[tid] = (g_s[2] * g_ws3[tid]) * inv_s3;
        s_bb[tid] = g_bf3[tid] * inv_s3;
    }

    int acc[12][4];
    #pragma unroll
    for (int nt = 0; nt < 12; ++nt)
        #pragma unroll
        for (int q = 0; q < 4; ++q) acc[nt][q] = 0;

    for (int kc = 0; kc < 6; ++kc) {
        __syncthreads();
        if (kc < 5) {
            int nb = (kc + 1) & 1;
            for (int idx = tid; idx < 768; idx += 256) {
                int r = idx >> 5, q4 = idx & 31;
                int n = n0 + 4 * q4, b = n / HW_, hw = n - b * HW_;
                CP16(smem_u32(&sm.pipe.a[nb][r * AS3 + 4 * q4]),
                     &g_y2i[(size_t)(b * 144 + (kc + 1) * 24 + r) * HW_ + hw]);
            }
            for (int idx = tid; idx < 576; idx += 256) {
                int co = idx / 6, seg = idx % 6;
                CP16(smem_u32(&sm.pipe.w[nb][co * WS + 4 * seg]),
                     &g_w3p[co * 144 + (kc + 1) * 24 + 4 * seg]);
            }
            CP_COMMIT();
            CP_WAIT1();
        } else {
            CP_WAIT0();
        }
        __syncthreads();
        const int* ab = sm.pipe.a[kc & 1];
        const int* wb = sm.pipe.w[kc & 1];

        #pragma unroll
        for (int s = 0; s < 3; ++s) {
            int a0 = ab[(8 * s + tg) * AS3 + p0 + g];
            int a1 = ab[(8 * s + tg) * AS3 + p0 + g + 8];
            int a2 = ab[(8 * s + 4 + tg) * AS3 + p0 + g];
            int a3 = ab[(8 * s + 4 + tg) * AS3 + p0 + g + 8];
            #pragma unroll
            for (int nt = 0; nt < 12; ++nt) {
                int b0 = wb[(8 * nt + g) * WS + 8 * s + tg];
                int b1 = wb[(8 * nt + g) * WS + 8 * s + 4 + tg];
                mma_s8(acc[nt][0], acc[nt][1], acc[nt][2], acc[nt][3],
                       a0, a1, a2, a3, b0, b1);
            }
        }
    }

    // ---- staged, coalesced epilogue: 2 rounds of 48 channels ----
    #pragma unroll
    for (int r = 0; r < 2; ++r) {
        __syncthreads();
        #pragma unroll
        for (int i = 0; i < 6; ++i) {
            int nt = 6 * r + i;
            int cl0 = 8 * i + 2 * tg;
            sm.stage[cl0 * STG_STRIDE + p0 + g]           = acc[nt][0];
            sm.stage[(cl0 + 1) * STG_STRIDE + p0 + g]     = acc[nt][1];
            sm.stage[cl0 * STG_STRIDE + p0 + g + 8]       = acc[nt][2];
            sm.stage[(cl0 + 1) * STG_STRIDE + p0 + g + 8] = acc[nt][3];
        }
        __syncthreads();
        int n = n0 + 4 * lane;
        int b = n / HW_;
        int hw = n - b * HW_;
        #pragma unroll
        for (int i = 0; i < 6; ++i) {
            int cl = 6 * wid + i;
            int c = 48 * r + cl;
            const int4 v = *(const int4*)&sm.stage[cl * STG_STRIDE + 4 * lane];
            const float al = s_al[c], bb = s_bb[c];
            size_t off = (size_t)(b * COUT + c) * HW_ + hw;
            float4 xv = *(const float4*)(x + off);
            float t0, q0, t1, q1, t2, q2, t3, q3;
            t0 = fmaf((float)v.x, al, bb); t0 = fmaf(xv.x, inv_s3, t0);
            q0 = rintf(fminf(fmaxf(t0, -127.f), 127.f));
            t1 = fmaf((float)v.y, al, bb); t1 = fmaf(xv.y, inv_s3, t1);
            q1 = rintf(fminf(fmaxf(t1, -127.f), 127.f));
            t2 = fmaf((float)v.z, al, bb); t2 = fmaf(xv.z, inv_s3, t2);
            q2 = rintf(fminf(fmaxf(t2, -127.f), 127.f));
            t3 = fmaf((float)v.w, al, bb); t3 = fmaf(xv.w, inv_s3, t3);
            q3 = rintf(fminf(fmaxf(t3, -127.f), 127.f));
            *(float4*)(out + off) = make_float4(q0 * s3, q1 * s3, q2 * s3, q3 * s3);
        }
    }
}

// ---------------- launch ----------------
extern "C" void kernel_launch(void* const* d_in, const int* in_sizes, int n_in,
                              void* d_out, int out_size) {
    const float* x  = (const float*)d_in[0];
    const float* w1 = (const float*)d_in[1];
    const float* g1 = (const float*)d_in[2];
    const float* b1 = (const float*)d_in[3];
    const float* m1 = (const float*)d_in[4];
    const float* v1 = (const float*)d_in[5];
    const float* w2 = (const float*)d_in[6];
    const float* g2 = (const float*)d_in[7];
    const float* b2 = (const float*)d_in[8];
    const float* m2 = (const float*)d_in[9];
    const float* v2 = (const float*)d_in[10];
    const float* w3 = (const float*)d_in[11];
    const float* g3 = (const float*)d_in[12];
    const float* b3 = (const float*)d_in[13];
    const float* m3 = (const float*)d_in[14];
    const float* v3 = (const float*)d_in[15];
    const float* r0 = (const float*)d_in[16];
    const float* r1 = (const float*)d_in[17];
    const float* r2 = (const float*)d_in[18];
    const float* r3 = (const float*)d_in[19];
    const int*   cl = (const int*)d_in[20];

    float* out = (float*)d_out;
    const int NOUT = B_ * COUT * HW_;
    float* s3out = (out_size > NOUT) ? out + NOUT : nullptr;

    // Raise unified L1/smem carveout so 3 CTAs (3 x ~48KB) fit per SM.
    // Host attribute calls: immediate, not captured, allocation-free, idempotent.
    cudaFuncSetAttribute(k1_conv1, cudaFuncAttributePreferredSharedMemoryCarveout, 70);
    cudaFuncSetAttribute(k3_conv3, cudaFuncAttributePreferredSharedMemoryCarveout, 70);

    prep_all<<<156, 256>>>(w1, g1, b1, m1, v1,
                           w2, g2, b2, m2, v2,
                           w3, g3, b3, m3, v3,
                           r0, r1, r2, r3, cl, s3out);
    k1_conv1<<<NPIX / 128, 256>>>(x);
    k2_dw<<<(B_ * CMID * 28) / 256, 256>>>();
    k3_conv3<<<NPIX / 128, 256>>>(x, out);
}

// round 11
// speedup vs baseline: 1.0254x; 1.0064x over previous
#include <cuda_runtime.h>
#include <math.h>
#include <stdint.h>

#define B_    64
#define CIN   96
#define CMID  576
#define COUT  96
#define HW_   784
#define NPIX  (B_*HW_)
#define NBITF 127.0f

__device__ float g_s[4];
__device__ float g_ws1[CMID], g_bf1[CMID];
__device__ float g_ws2[CMID], g_bf2[CMID];
__device__ float g_ws3[COUT], g_bf3[COUT];
__device__ __align__(16) int g_w1p[CMID * 32];    // [co][slot tg*8+m], m=0..5
__device__ __align__(16) int g_w2p[CMID * 3];
__device__ __align__(16) int g_w3p[COUT * 144];   // [co][chunk kc][slot tg*4+m]
__device__ __align__(16) signed char g_y1[B_ * CMID * HW_];   // channel-major
__device__ __align__(16) int g_y2i[B_ * 144 * HW_];           // interleaved words

// ---------------- cp.async helpers ----------------
__device__ __forceinline__ uint32_t smem_u32(const void* p) {
    uint32_t a;
    asm("{ .reg .u64 t; cvta.to.shared.u64 t, %1; cvt.u32.u64 %0, t; }" : "=r"(a) : "l"(p));
    return a;
}
#define CP16(dst, src) \
    asm volatile("cp.async.cg.shared.global [%0], [%1], 16;" :: "r"(dst), "l"(src))
#define CP_COMMIT() asm volatile("cp.async.commit_group;")
#define CP_WAIT0()  asm volatile("cp.async.wait_group 0;")
#define CP_WAIT1()  asm volatile("cp.async.wait_group 1;")

// ---------------- prep ----------------
__global__ void __launch_bounds__(256) prep_all(
    const float* __restrict__ w1, const float* __restrict__ g1, const float* __restrict__ b1,
    const float* __restrict__ m1, const float* __restrict__ v1,
    const float* __restrict__ w2, const float* __restrict__ g2, const float* __restrict__ b2,
    const float* __restrict__ m2, const float* __restrict__ v2,
    const float* __restrict__ w3, const float* __restrict__ g3, const float* __restrict__ b3,
    const float* __restrict__ m3, const float* __restrict__ v3,
    const float* __restrict__ r0, const float* __restrict__ r1,
    const float* __restrict__ r2, const float* __restrict__ r3,
    const int* __restrict__ cl, float* s3out) {
    __shared__ float sv[8][CMID];
    __shared__ signed char qs[8][CMID];
    const int w = threadIdx.x >> 5, lane = threadIdx.x & 31;
    const int gw = blockIdx.x * 8 + w;

    if (blockIdx.x == 0 && threadIdx.x == 0) {
        int c = cl[0];
        g_s[0] = r0[c] / NBITF;
        g_s[1] = r1[c] / NBITF;
        g_s[2] = r2[c] / NBITF;
        float s3 = r3[c] / NBITF;
        g_s[3] = s3;
        if (s3out) *s3out = s3;
    }

    if (gw < CMID) {
        int co = gw;
        float scale = g1[co] / sqrtf(v1[co] + 1e-5f);
        float m = 0.f;
        for (int k = lane; k < CIN; k += 32) {
            float v = w1[co * CIN + k] * scale;
            sv[w][k] = v;
            m = fmaxf(m, fabsf(v));
        }
        #pragma unroll
        for (int s = 16; s > 0; s >>= 1) m = fmaxf(m, __shfl_xor_sync(0xFFFFFFFF, m, s));
        float sc = m / NBITF;
        if (lane == 0) { g_ws1[co] = sc; g_bf1[co] = b1[co] - m1[co] * scale; }
        for (int k = lane; k < CIN; k += 32) {
            float q = fminf(fmaxf(rintf(sv[w][k] / sc), -127.f), 127.f);
            qs[w][k] = (signed char)q;
        }
        __syncwarp();
        if (lane < 24) {
            // orig word = lane (channels 4*lane..+3); slot = tg*8 + m  (tg=lane&3, m=lane>>2)
            const signed char* q = &qs[w][4 * lane];
            int word = (q[0] & 0xFF) | ((q[1] & 0xFF) << 8) |
                       ((q[2] & 0xFF) << 16) | ((q[3] & 0xFF) << 24);
            g_w1p[co * 32 + (lane & 3) * 8 + (lane >> 2)] = word;
        }
    } else if (gw < 2 * CMID) {
        int co = gw - CMID;
        float scale = g2[co] / sqrtf(v2[co] + 1e-5f);
        float m = 0.f;
        if (lane < 9) {
            float v = w2[co * 9 + lane] * scale;
            sv[w][lane] = v;
            m = fabsf(v);
        }
        #pragma unroll
        for (int s = 16; s > 0; s >>= 1) m = fmaxf(m, __shfl_xor_sync(0xFFFFFFFF, m, s));
        float sc = m / NBITF;
        if (lane == 0) { g_ws2[co] = sc; g_bf2[co] = b2[co] - m2[co] * scale; }
        if (lane < 9) {
            float q = fminf(fmaxf(rintf(sv[w][lane] / sc), -127.f), 127.f);
            qs[w][lane] = (signed char)q;
        }
        __syncwarp();
        if (lane < 3) {
            const signed char* q = &qs[w][3 * lane];
            g_w2p[co * 3 + lane] = (q[0] & 0xFF) | ((q[1] & 0xFF) << 8) | ((q[2] & 0xFF) << 16);
        }
    } else {
        int co = gw - 2 * CMID;
        float scale = g3[co] / sqrtf(v3[co] + 1e-5f);
        float m = 0.f;
        for (int k = lane; k < CMID; k += 32) {
            float v = w3[co * CMID + k] * scale;
            sv[w][k] = v;
            m = fmaxf(m, fabsf(v));
        }
        #pragma unroll
        for (int s = 16; s > 0; s >>= 1) m = fmaxf(m, __shfl_xor_sync(0xFFFFFFFF, m, s));
        float sc = m / NBITF;
        if (lane == 0) { g_ws3[co] = sc; g_bf3[co] = b3[co] - m3[co] * scale; }
        for (int k = lane; k < CMID; k += 32) {
            float q = fminf(fmaxf(rintf(sv[w][k] / sc), -127.f), 127.f);
            qs[w][k] = (signed char)q;
        }
        __syncwarp();
        for (int p = lane; p < 144; p += 32) {
            // orig word p: chunk kc = p>>4, local w' = p&15, tg = w'&3, m = w'>>2
            const signed char* q = &qs[w][4 * p];
            int word = (q[0] & 0xFF) | ((q[1] & 0xFF) << 8) |
                       ((q[2] & 0xFF) << 16) | ((q[3] & 0xFF) << 24);
            int kc = p >> 4, wl = p & 15;
            g_w3p[co * 144 + kc * 16 + (wl & 3) * 4 + (wl >> 2)] = word;
        }
    }
}

// ---------------- IMMA + requant ----------------
__device__ __forceinline__ void mma_s8(int& d0, int& d1, int& d2, int& d3,
                                       int a0, int a1, int a2, int a3,
                                       int b0, int b1) {
    asm volatile(
        "mma.sync.aligned.m16n8k32.row.col.s32.s8.s8.s32 "
        "{%0,%1,%2,%3}, {%4,%5,%6,%7}, {%8,%9}, {%0,%1,%2,%3};"
        : "+r"(d0), "+r"(d1), "+r"(d2), "+r"(d3)
        : "r"(a0), "r"(a1), "r"(a2), "r"(a3), "r"(b0), "r"(b1));
}
__device__ __forceinline__ int requant_sat(int acc, float al6, float bb6, float C) {
    float z = __saturatef(fmaf((float)acc, al6, bb6));
    int q = __float2int_rn(z * C);
    return q > 127 ? 127 : q;
}

// ---------------- k1: quant(x) + 1x1 conv (96->576) IMMA, 12 co-chunks of 48 ----------------
#define AS1 136
#define WS1 36   // smem words per co: slots tg*8+m (m=0..5), conflict-free phases
__global__ void __launch_bounds__(256, 3) k1_conv1(const float* __restrict__ x) {
    __shared__ __align__(16) int a_sm[24 * AS1];       // 13056 B
    __shared__ __align__(16) int w_sm[2][48 * WS1];    // 13824 B
    __shared__ float s_al[CMID], s_bb[CMID];           // 4608 B
    __shared__ __align__(16) signed char o_sm[8 * 512];

    const int tid = threadIdx.x;
    const int n0 = blockIdx.x * 128;
    const float s0 = g_s[0];
    const float inv_s0 = 1.0f / s0;
    const float C1 = 6.0f / g_s[1];
    const float SIXTH = 1.0f / 6.0f;

    // prologue: weight chunk 0 (co 0..47): 48 co x 8 int4
    for (int idx = tid; idx < 384; idx += 256) {
        int co = idx >> 3, j = idx & 7;
        CP16(smem_u32(&w_sm[0][co * WS1 + 4 * j]), &g_w1p[co * 32 + 4 * j]);
    }
    CP_COMMIT();

    for (int i = tid; i < CMID; i += 256) {
        s_al[i] = (s0 * g_ws1[i]) * SIXTH;
        s_bb[i] = g_bf1[i] * SIXTH;
    }

    // quantize x tile (96ch x 128px) into k-packed smem
    for (int idx = tid; idx < 768; idx += 256) {
        int cg = idx >> 5, q4 = idx & 31;
        int n = n0 + 4 * q4;
        int b = n / HW_;
        int hw = n - b * HW_;
        int q[4][4];
        #pragma unroll
        for (int j = 0; j < 4; ++j) {
            float4 v = *(const float4*)(x + ((size_t)(b * CIN + 4 * cg + j) * HW_ + hw));
            float f;
            f = fminf(fmaxf(rintf(v.x * inv_s0), -127.f), 127.f); q[j][0] = (int)f;
            f = fminf(fmaxf(rintf(v.y * inv_s0), -127.f), 127.f); q[j][1] = (int)f;
            f = fminf(fmaxf(rintf(v.z * inv_s0), -127.f), 127.f); q[j][2] = (int)f;
            f = fminf(fmaxf(rintf(v.w * inv_s0), -127.f), 127.f); q[j][3] = (int)f;
        }
        int w[4];
        #pragma unroll
        for (int p = 0; p < 4; ++p) {
            int lo = __byte_perm(q[0][p], q[1][p], 0x0040);
            int hi = __byte_perm(q[2][p], q[3][p], 0x0040);
            w[p] = __byte_perm(lo, hi, 0x5410);
        }
        *(int4*)&a_sm[cg * AS1 + 4 * q4] = make_int4(w[0], w[1], w[2], w[3]);
    }

    const int lane = tid & 31, wid = tid >> 5;
    const int g = lane >> 2, tg = lane & 3;
    const int p0 = wid * 16;
    const int nn = n0 + p0;
    const int bw = nn / HW_;
    const int hww = nn - bw * HW_;

    __syncthreads();

    int A0[3], A1[3], A2[3], A3[3];
    #pragma unroll
    for (int s = 0; s < 3; ++s) {
        A0[s] = a_sm[(8 * s + tg) * AS1 + p0 + g];
        A1[s] = a_sm[(8 * s + tg) * AS1 + p0 + g + 8];
        A2[s] = a_sm[(8 * s + 4 + tg) * AS1 + p0 + g];
        A3[s] = a_sm[(8 * s + 4 + tg) * AS1 + p0 + g + 8];
    }

    for (int kc = 0; kc < 12; ++kc) {      // 12 chunks of 48 output channels
        __syncthreads();
        if (kc < 11) {
            for (int idx = tid; idx < 384; idx += 256) {
                int co = idx >> 3, j = idx & 7;
                CP16(smem_u32(&w_sm[(kc + 1) & 1][co * WS1 + 4 * j]),
                     &g_w1p[((kc + 1) * 48 + co) * 32 + 4 * j]);
            }
            CP_COMMIT();
            CP_WAIT1();
        } else {
            CP_WAIT0();
        }
        __syncthreads();
        const int* wb = w_sm[kc & 1];

        for (int ct = 0; ct < 6; ++ct) {
            const int gct = kc * 6 + ct;   // global co-tile (8 co each)
            const int co0 = ct * 8;
            int4 wv = *(const int4*)&wb[(co0 + g) * WS1 + tg * 8];
            int2 wv2 = *(const int2*)&wb[(co0 + g) * WS1 + tg * 8 + 4];
            int d0 = 0, d1 = 0, d2 = 0, d3 = 0;
            mma_s8(d0, d1, d2, d3, A0[0], A1[0], A2[0], A3[0], wv.x, wv.y);
            mma_s8(d0, d1, d2, d3, A0[1], A1[1], A2[1], A3[1], wv.z, wv.w);
            mma_s8(d0, d1, d2, d3, A0[2], A1[2], A2[2], A3[2], wv2.x, wv2.y);

            const int cA = gct * 8 + 2 * tg, cB = cA + 1;
            const float alA = s_al[cA], bbA = s_bb[cA];
            const float alB = s_al[cB], bbB = s_bb[cB];
            signed char* ob = o_sm + wid * 512 + (gct & 3) * 128;
            ob[(2 * tg) * 16 + g]         = (signed char)requant_sat(d0, alA, bbA, C1);
            ob[(2 * tg + 1) * 16 + g]     = (signed char)requant_sat(d1, alB, bbB, C1);
            ob[(2 * tg) * 16 + g + 8]     = (signed char)requant_sat(d2, alA, bbA, C1);
            ob[(2 * tg + 1) * 16 + g + 8] = (signed char)requant_sat(d3, alB, bbB, C1);

            if ((gct & 3) == 3) {
                __syncwarp();
                int4 v = *(const int4*)(o_sm + wid * 512 + lane * 16);
                int tb = lane >> 3, col = lane & 7;
                int cog = (gct - 3 + tb) * 8 + col;
                *(int4*)(g_y1 + (size_t)(bw * CMID + cog) * HW_ + hww) = v;
                __syncwarp();
            }
        }
    }
}

// ---------------- k2: depthwise 3x3 -> interleaved g_y2i ----------------
__global__ void __launch_bounds__(256) k2_dw() {
    int t = blockIdx.x * 256 + threadIdx.x;
    int j = t & 3;
    int Q = t >> 2;
    int h = Q % 28;
    int bcg = Q / 28;
    int cg = bcg % 144;
    int b = bcg / 144;
    int c = 4 * cg + j;
    int base = (b * CMID + c) * HW_;

    int r0[8], r1[8], r2[8];
    const int* p1 = (const int*)(g_y1 + base + h * 28);
    #pragma unroll
    for (int q = 0; q < 7; ++q) r1[q] = p1[q];
    r1[7] = 0;
    if (h > 0) {
        const int* p0 = p1 - 7;
        #pragma unroll
        for (int q = 0; q < 7; ++q) r0[q] = p0[q];
    } else {
        #pragma unroll
        for (int q = 0; q < 7; ++q) r0[q] = 0;
    }
    r0[7] = 0;
    if (h < 27) {
        const int* p2 = p1 + 7;
        #pragma unroll
        for (int q = 0; q < 7; ++q) r2[q] = p2[q];
    } else {
        #pragma unroll
        for (int q = 0; q < 7; ++q) r2[q] = 0;
    }
    r2[7] = 0;

    int wp0 = g_w2p[c * 3 + 0];
    int wp1 = g_w2p[c * 3 + 1];
    int wp2 = g_w2p[c * 3 + 2];
    const float SIXTH = 1.0f / 6.0f;
    float al = (g_s[1] * g_ws2[c]) * SIXTH;
    float bb = g_bf2[c] * SIXTH;
    float C2 = 6.0f / g_s[2];

    int ow[7];
    int qv[4];
    #pragma unroll
    for (int w = 0; w < 28; ++w) {
        int op0, op1, op2;
        if (w == 0) {
            op0 = __byte_perm(r0[0], 0, 0x2104);
            op1 = __byte_perm(r1[0], 0, 0x2104);
            op2 = __byte_perm(r2[0], 0, 0x2104);
        } else {
            int s = w - 1, q = s >> 2, o = s & 3;
            unsigned sel = 0x3210u + (unsigned)o * 0x1111u;
            op0 = __byte_perm(r0[q], r0[q + 1], sel);
            op1 = __byte_perm(r1[q], r1[q + 1], sel);
            op2 = __byte_perm(r2[q], r2[q + 1], sel);
        }
        int acc = __dp4a(op0, wp0, __dp4a(op1, wp1, __dp4a(op2, wp2, 0)));
        qv[w & 3] = requant_sat(acc, al, bb, C2);
        if ((w & 3) == 3) {
            int lo = __byte_perm(qv[0], qv[1], 0x0040);
            int hi = __byte_perm(qv[2], qv[3], 0x0040);
            ow[w >> 2] = __byte_perm(lo, hi, 0x5410);
        }
    }

    int lane = threadIdx.x & 31;
    int qb = lane & ~3;
    int ob = (b * 144 + cg) * HW_ + h * 28;
    unsigned selj = (unsigned)j | ((unsigned)(j + 4) << 4);
    #pragma unroll
    for (int q = 0; q < 7; ++q) {
        int v0 = __shfl_sync(0xFFFFFFFFu, ow[q], qb + 0);
        int v1 = __shfl_sync(0xFFFFFFFFu, ow[q], qb + 1);
        int v2 = __shfl_sync(0xFFFFFFFFu, ow[q], qb + 2);
        int v3 = __shfl_sync(0xFFFFFFFFu, ow[q], qb + 3);
        int s1 = __byte_perm(v0, v1, selj);
        int s2 = __byte_perm(v2, v3, selj);
        g_y2i[ob + 4 * q + j] = __byte_perm(s1, s2, 0x5410);
    }
}

// ---------------- k3: 1x1 conv (576->96) IMMA, 9 K-chunks of 64ch, ~30.5KB smem ----------------
#define AS3 136
#define STG_STRIDE 132
__global__ void __launch_bounds__(256, 3) k3_conv3(const float* __restrict__ x,
                                                   float* __restrict__ out) {
    __shared__ union {
        struct {
            int a[2][16 * AS3];   // 17408 B
            int w[2][96 * 16];    // 12288 B
        } pipe;
        int stage[48 * STG_STRIDE];  // 25344 B (epilogue reuse)
    } sm;
    __shared__ float s_al[96], s_bb[96];

    const int tid = threadIdx.x, lane = tid & 31, wid = tid >> 5;
    const int g = lane >> 2, tg = lane & 3;
    const int n0 = blockIdx.x * 128;
    const int p0 = wid * 16;
    const float s3 = g_s[3], inv_s3 = 1.0f / s3;

    // prologue: chunk 0 (A: 16 cg rows x 128 px; W: 96 co x 16 words)
    for (int idx = tid; idx < 512; idx += 256) {
        int r = idx >> 5, q4 = idx & 31;
        int n = n0 + 4 * q4, b = n / HW_, hw = n - b * HW_;
        CP16(smem_u32(&sm.pipe.a[0][r * AS3 + 4 * q4]),
             &g_y2i[(size_t)(b * 144 + r) * HW_ + hw]);
    }
    for (int idx = tid; idx < 384; idx += 256) {
        int co = idx >> 2, j = idx & 3;
        CP16(smem_u32(&sm.pipe.w[0][co * 16 + 4 * j]), &g_w3p[co * 144 + 4 * j]);
    }
    CP_COMMIT();

    if (tid < 96) {
        s_al[tid] = (g_s[2] * g_ws3[tid]) * inv_s3;
        s_bb[tid] = g_bf3[tid] * inv_s3;
    }

    int acc[12][4];
    #pragma unroll
    for (int nt = 0; nt < 12; ++nt)
        #pragma unroll
        for (int q = 0; q < 4; ++q) acc[nt][q] = 0;

    for (int kc = 0; kc < 9; ++kc) {        // 9 K-chunks of 64 channels (16 cgs)
        __syncthreads();
        if (kc < 8) {
            int nb = (kc + 1) & 1;
            for (int idx = tid; idx < 512; idx += 256) {
                int r = idx >> 5, q4 = idx & 31;
                int n = n0 + 4 * q4, b = n / HW_, hw = n - b * HW_;
                CP16(smem_u32(&sm.pipe.a[nb][r * AS3 + 4 * q4]),
                     &g_y2i[(size_t)(b * 144 + (kc + 1) * 16 + r) * HW_ + hw]);
            }
            for (int idx = tid; idx < 384; idx += 256) {
                int co = idx >> 2, j = idx & 3;
                CP16(smem_u32(&sm.pipe.w[nb][co * 16 + 4 * j]),
                     &g_w3p[co * 144 + (kc + 1) * 16 + 4 * j]);
            }
            CP_COMMIT();
            CP_WAIT1();
        } else {
            CP_WAIT0();
        }
        __syncthreads();
        const int* ab = sm.pipe.a[kc & 1];
        const int* wb = sm.pipe.w[kc & 1];

        // A fragments for 2 K32-steps
        int a00 = ab[tg * AS3 + p0 + g];
        int a01 = ab[tg * AS3 + p0 + g + 8];
        int a02 = ab[(4 + tg) * AS3 + p0 + g];
        int a03 = ab[(4 + tg) * AS3 + p0 + g + 8];
        int a10 = ab[(8 + tg) * AS3 + p0 + g];
        int a11 = ab[(8 + tg) * AS3 + p0 + g + 8];
        int a12 = ab[(12 + tg) * AS3 + p0 + g];
        int a13 = ab[(12 + tg) * AS3 + p0 + g + 8];

        #pragma unroll
        for (int nt = 0; nt < 12; ++nt) {
            int4 wv = *(const int4*)&wb[(8 * nt + g) * 16 + tg * 4];
            mma_s8(acc[nt][0], acc[nt][1], acc[nt][2], acc[nt][3],
                   a00, a01, a02, a03, wv.x, wv.y);
            mma_s8(acc[nt][0], acc[nt][1], acc[nt][2], acc[nt][3],
                   a10, a11, a12, a13, wv.z, wv.w);
        }
    }

    // ---- staged, coalesced epilogue: 2 rounds of 48 channels ----
    #pragma unroll
    for (int r = 0; r < 2; ++r) {
        __syncthreads();
        #pragma unroll
        for (int i = 0; i < 6; ++i) {
            int nt = 6 * r + i;
            int cl0 = 8 * i + 2 * tg;
            sm.stage[cl0 * STG_STRIDE + p0 + g]           = acc[nt][0];
            sm.stage[(cl0 + 1) * STG_STRIDE + p0 + g]     = acc[nt][1];
            sm.stage[cl0 * STG_STRIDE + p0 + g + 8]       = acc[nt][2];
            sm.stage[(cl0 + 1) * STG_STRIDE + p0 + g + 8] = acc[nt][3];
        }
        __syncthreads();
        int n = n0 + 4 * lane;
        int b = n / HW_;
        int hw = n - b * HW_;
        #pragma unroll
        for (int i = 0; i < 6; ++i) {
            int cl = 6 * wid + i;
            int c = 48 * r + cl;
            const int4 v = *(const int4*)&sm.stage[cl * STG_STRIDE + 4 * lane];
            const float al = s_al[c], bb = s_bb[c];
            size_t off = (size_t)(b * COUT + c) * HW_ + hw;
            float4 xv = *(const float4*)(x + off);
            float t0, q0, t1, q1, t2, q2, t3, q3;
            t0 = fmaf((float)v.x, al, bb); t0 = fmaf(xv.x, inv_s3, t0);
            q0 = rintf(fminf(fmaxf(t0, -127.f), 127.f));
            t1 = fmaf((float)v.y, al, bb); t1 = fmaf(xv.y, inv_s3, t1);
            q1 = rintf(fminf(fmaxf(t1, -127.f), 127.f));
            t2 = fmaf((float)v.z, al, bb); t2 = fmaf(xv.z, inv_s3, t2);
            q2 = rintf(fminf(fmaxf(t2, -127.f), 127.f));
            t3 = fmaf((float)v.w, al, bb); t3 = fmaf(xv.w, inv_s3, t3);
            q3 = rintf(fminf(fmaxf(t3, -127.f), 127.f));
            *(float4*)(out + off) = make_float4(q0 * s3, q1 * s3, q2 * s3, q3 * s3);
        }
    }
}

// ---------------- launch ----------------
extern "C" void kernel_launch(void* const* d_in, const int* in_sizes, int n_in,
                              void* d_out, int out_size) {
    const float* x  = (const float*)d_in[0];
    const float* w1 = (const float*)d_in[1];
    const float* g1 = (const float*)d_in[2];
    const float* b1 = (const float*)d_in[3];
    const float* m1 = (const float*)d_in[4];
    const float* v1 = (const float*)d_in[5];
    const float* w2 = (const float*)d_in[6];
    const float* g2 = (const float*)d_in[7];
    const float* b2 = (const float*)d_in[8];
    const float* m2 = (const float*)d_in[9];
    const float* v2 = (const float*)d_in[10];
    const float* w3 = (const float*)d_in[11];
    const float* g3 = (const float*)d_in[12];
    const float* b3 = (const float*)d_in[13];
    const float* m3 = (const float*)d_in[14];
    const float* v3 = (const float*)d_in[15];
    const float* r0 = (const float*)d_in[16];
    const float* r1 = (const float*)d_in[17];
    const float* r2 = (const float*)d_in[18];
    const float* r3 = (const float*)d_in[19];
    const int*   cl = (const int*)d_in[20];

    float* out = (float*)d_out;
    const int NOUT = B_ * COUT * HW_;
    float* s3out = (out_size > NOUT) ? out + NOUT : nullptr;

    cudaFuncSetAttribute(k1_conv1, cudaFuncAttributePreferredSharedMemoryCarveout, 70);
    cudaFuncSetAttribute(k3_conv3, cudaFuncAttributePreferredSharedMemoryCarveout, 70);

    prep_all<<<156, 256>>>(w1, g1, b1, m1, v1,
                           w2, g2, b2, m2, v2,
                           w3, g3, b3, m3, v3,
                           r0, r1, r2, r3, cl, s3out);
    k1_conv1<<<NPIX / 128, 256>>>(x);
    k2_dw<<<(B_ * CMID * 28) / 256, 256>>>();
    k3_conv3<<<NPIX / 128, 256>>>(x, out);
}

// round 12
// speedup vs baseline: 1.0305x; 1.0050x over previous
#include <cuda_runtime.h>
#include <math.h>
#include <stdint.h>

#define B_    64
#define CIN   96
#define CMID  576
#define COUT  96
#define HW_   784
#define NPIX  (B_*HW_)
#define NBITF 127.0f

__device__ float g_s[4];
__device__ float g_ws1[CMID], g_bf1[CMID];
__device__ float g_ws2[CMID], g_bf2[CMID];
__device__ float g_ws3[COUT], g_bf3[COUT];
__device__ __align__(16) int g_w1p[CMID * 32];    // [co][slot tg*8+m], m=0..5
__device__ __align__(16) int g_w2p[CMID * 3];
__device__ __align__(16) int g_w3p[COUT * 144];   // [co][chunk kc][slot tg*4+m]
__device__ __align__(16) signed char g_y1[B_ * CMID * HW_];   // channel-major
__device__ __align__(16) int g_y2i[B_ * 144 * HW_];           // interleaved words

// ---------------- cp.async helpers ----------------
__device__ __forceinline__ uint32_t smem_u32(const void* p) {
    uint32_t a;
    asm("{ .reg .u64 t; cvta.to.shared.u64 t, %1; cvt.u32.u64 %0, t; }" : "=r"(a) : "l"(p));
    return a;
}
#define CP16(dst, src) \
    asm volatile("cp.async.cg.shared.global [%0], [%1], 16;" :: "r"(dst), "l"(src))
#define CP_COMMIT() asm volatile("cp.async.commit_group;")
#define CP_WAIT0()  asm volatile("cp.async.wait_group 0;")
#define CP_WAIT1()  asm volatile("cp.async.wait_group 1;")

// ---------------- prep ----------------
__global__ void __launch_bounds__(256) prep_all(
    const float* __restrict__ w1, const float* __restrict__ g1, const float* __restrict__ b1,
    const float* __restrict__ m1, const float* __restrict__ v1,
    const float* __restrict__ w2, const float* __restrict__ g2, const float* __restrict__ b2,
    const float* __restrict__ m2, const float* __restrict__ v2,
    const float* __restrict__ w3, const float* __restrict__ g3, const float* __restrict__ b3,
    const float* __restrict__ m3, const float* __restrict__ v3,
    const float* __restrict__ r0, const float* __restrict__ r1,
    const float* __restrict__ r2, const float* __restrict__ r3,
    const int* __restrict__ cl, float* s3out) {
    __shared__ float sv[8][CMID];
    __shared__ signed char qs[8][CMID];
    const int w = threadIdx.x >> 5, lane = threadIdx.x & 31;
    const int gw = blockIdx.x * 8 + w;

    if (blockIdx.x == 0 && threadIdx.x == 0) {
        int c = cl[0];
        g_s[0] = r0[c] / NBITF;
        g_s[1] = r1[c] / NBITF;
        g_s[2] = r2[c] / NBITF;
        float s3 = r3[c] / NBITF;
        g_s[3] = s3;
        if (s3out) *s3out = s3;
    }

    if (gw < CMID) {
        int co = gw;
        float scale = g1[co] / sqrtf(v1[co] + 1e-5f);
        float m = 0.f;
        for (int k = lane; k < CIN; k += 32) {
            float v = w1[co * CIN + k] * scale;
            sv[w][k] = v;
            m = fmaxf(m, fabsf(v));
        }
        #pragma unroll
        for (int s = 16; s > 0; s >>= 1) m = fmaxf(m, __shfl_xor_sync(0xFFFFFFFF, m, s));
        float sc = m / NBITF;
        if (lane == 0) { g_ws1[co] = sc; g_bf1[co] = b1[co] - m1[co] * scale; }
        for (int k = lane; k < CIN; k += 32) {
            float q = fminf(fmaxf(rintf(sv[w][k] / sc), -127.f), 127.f);
            qs[w][k] = (signed char)q;
        }
        __syncwarp();
        if (lane < 24) {
            const signed char* q = &qs[w][4 * lane];
            int word = (q[0] & 0xFF) | ((q[1] & 0xFF) << 8) |
                       ((q[2] & 0xFF) << 16) | ((q[3] & 0xFF) << 24);
            g_w1p[co * 32 + (lane & 3) * 8 + (lane >> 2)] = word;
        }
    } else if (gw < 2 * CMID) {
        int co = gw - CMID;
        float scale = g2[co] / sqrtf(v2[co] + 1e-5f);
        float m = 0.f;
        if (lane < 9) {
            float v = w2[co * 9 + lane] * scale;
            sv[w][lane] = v;
            m = fabsf(v);
        }
        #pragma unroll
        for (int s = 16; s > 0; s >>= 1) m = fmaxf(m, __shfl_xor_sync(0xFFFFFFFF, m, s));
        float sc = m / NBITF;
        if (lane == 0) { g_ws2[co] = sc; g_bf2[co] = b2[co] - m2[co] * scale; }
        if (lane < 9) {
            float q = fminf(fmaxf(rintf(sv[w][lane] / sc), -127.f), 127.f);
            qs[w][lane] = (signed char)q;
        }
        __syncwarp();
        if (lane < 3) {
            const signed char* q = &qs[w][3 * lane];
            g_w2p[co * 3 + lane] = (q[0] & 0xFF) | ((q[1] & 0xFF) << 8) | ((q[2] & 0xFF) << 16);
        }
    } else {
        int co = gw - 2 * CMID;
        float scale = g3[co] / sqrtf(v3[co] + 1e-5f);
        float m = 0.f;
        for (int k = lane; k < CMID; k += 32) {
            float v = w3[co * CMID + k] * scale;
            sv[w][k] = v;
            m = fmaxf(m, fabsf(v));
        }
        #pragma unroll
        for (int s = 16; s > 0; s >>= 1) m = fmaxf(m, __shfl_xor_sync(0xFFFFFFFF, m, s));
        float sc = m / NBITF;
        if (lane == 0) { g_ws3[co] = sc; g_bf3[co] = b3[co] - m3[co] * scale; }
        for (int k = lane; k < CMID; k += 32) {
            float q = fminf(fmaxf(rintf(sv[w][k] / sc), -127.f), 127.f);
            qs[w][k] = (signed char)q;
        }
        __syncwarp();
        for (int p = lane; p < 144; p += 32) {
            const signed char* q = &qs[w][4 * p];
            int word = (q[0] & 0xFF) | ((q[1] & 0xFF) << 8) |
                       ((q[2] & 0xFF) << 16) | ((q[3] & 0xFF) << 24);
            int kc = p >> 4, wl = p & 15;
            g_w3p[co * 144 + kc * 16 + (wl & 3) * 4 + (wl >> 2)] = word;
        }
    }
}

// ---------------- IMMA + requant ----------------
__device__ __forceinline__ void mma_s8(int& d0, int& d1, int& d2, int& d3,
                                       int a0, int a1, int a2, int a3,
                                       int b0, int b1) {
    asm volatile(
        "mma.sync.aligned.m16n8k32.row.col.s32.s8.s8.s32 "
        "{%0,%1,%2,%3}, {%4,%5,%6,%7}, {%8,%9}, {%0,%1,%2,%3};"
        : "+r"(d0), "+r"(d1), "+r"(d2), "+r"(d3)
        : "r"(a0), "r"(a1), "r"(a2), "r"(a3), "r"(b0), "r"(b1));
}
__device__ __forceinline__ int requant_sat(int acc, float al6, float bb6, float C) {
    float z = __saturatef(fmaf((float)acc, al6, bb6));
    int q = __float2int_rn(z * C);
    return q > 127 ? 127 : q;
}

// ---------------- k1: quant(x) + 1x1 conv (96->576) IMMA, triple-buffered weights ----------------
#define AS1 136
#define WS1 36
__global__ void __launch_bounds__(256, 3) k1_conv1(const float* __restrict__ x) {
    __shared__ __align__(16) int a_sm[24 * AS1];       // 13056 B
    __shared__ __align__(16) int w_sm[3][48 * WS1];    // 20736 B
    __shared__ float s_al[CMID], s_bb[CMID];           // 4608 B
    __shared__ __align__(16) signed char o_sm[8 * 512];

    const int tid = threadIdx.x;
    const int n0 = blockIdx.x * 128;
    const float s0 = g_s[0];
    const float inv_s0 = 1.0f / s0;
    const float C1 = 6.0f / g_s[1];
    const float SIXTH = 1.0f / 6.0f;

    // prologue: weight chunks 0 and 1
    #pragma unroll
    for (int c0 = 0; c0 < 2; ++c0) {
        for (int idx = tid; idx < 384; idx += 256) {
            int co = idx >> 3, j = idx & 7;
            CP16(smem_u32(&w_sm[c0][co * WS1 + 4 * j]),
                 &g_w1p[(c0 * 48 + co) * 32 + 4 * j]);
        }
        CP_COMMIT();
    }

    for (int i = tid; i < CMID; i += 256) {
        s_al[i] = (s0 * g_ws1[i]) * SIXTH;
        s_bb[i] = g_bf1[i] * SIXTH;
    }

    // quantize x tile (96ch x 128px) into k-packed smem
    for (int idx = tid; idx < 768; idx += 256) {
        int cg = idx >> 5, q4 = idx & 31;
        int n = n0 + 4 * q4;
        int b = n / HW_;
        int hw = n - b * HW_;
        int q[4][4];
        #pragma unroll
        for (int j = 0; j < 4; ++j) {
            float4 v = *(const float4*)(x + ((size_t)(b * CIN + 4 * cg + j) * HW_ + hw));
            float f;
            f = fminf(fmaxf(rintf(v.x * inv_s0), -127.f), 127.f); q[j][0] = (int)f;
            f = fminf(fmaxf(rintf(v.y * inv_s0), -127.f), 127.f); q[j][1] = (int)f;
            f = fminf(fmaxf(rintf(v.z * inv_s0), -127.f), 127.f); q[j][2] = (int)f;
            f = fminf(fmaxf(rintf(v.w * inv_s0), -127.f), 127.f); q[j][3] = (int)f;
        }
        int w[4];
        #pragma unroll
        for (int p = 0; p < 4; ++p) {
            int lo = __byte_perm(q[0][p], q[1][p], 0x0040);
            int hi = __byte_perm(q[2][p], q[3][p], 0x0040);
            w[p] = __byte_perm(lo, hi, 0x5410);
        }
        *(int4*)&a_sm[cg * AS1 + 4 * q4] = make_int4(w[0], w[1], w[2], w[3]);
    }

    const int lane = tid & 31, wid = tid >> 5;
    const int g = lane >> 2, tg = lane & 3;
    const int p0 = wid * 16;
    const int nn = n0 + p0;
    const int bw = nn / HW_;
    const int hww = nn - bw * HW_;

    __syncthreads();

    int A0[3], A1[3], A2[3], A3[3];
    #pragma unroll
    for (int s = 0; s < 3; ++s) {
        A0[s] = a_sm[(8 * s + tg) * AS1 + p0 + g];
        A1[s] = a_sm[(8 * s + tg) * AS1 + p0 + g + 8];
        A2[s] = a_sm[(8 * s + 4 + tg) * AS1 + p0 + g];
        A3[s] = a_sm[(8 * s + 4 + tg) * AS1 + p0 + g + 8];
    }

    int rb = 0, lb = 2;                    // read buf, load buf (for chunk kc+2)
    for (int kc = 0; kc < 12; ++kc) {      // 12 chunks of 48 output channels
        if (kc < 11) { CP_WAIT1(); } else { CP_WAIT0(); }
        __syncthreads();                   // chunk kc visible; readers of buf lb done (iter kc-1)
        if (kc + 2 <= 11) {
            for (int idx = tid; idx < 384; idx += 256) {
                int co = idx >> 3, j = idx & 7;
                CP16(smem_u32(&w_sm[lb][co * WS1 + 4 * j]),
                     &g_w1p[((kc + 2) * 48 + co) * 32 + 4 * j]);
            }
            CP_COMMIT();
        }
        const int* wb = w_sm[rb];

        for (int ct = 0; ct < 6; ++ct) {
            const int gct = kc * 6 + ct;
            const int co0 = ct * 8;
            int4 wv = *(const int4*)&wb[(co0 + g) * WS1 + tg * 8];
            int2 wv2 = *(const int2*)&wb[(co0 + g) * WS1 + tg * 8 + 4];
            int d0 = 0, d1 = 0, d2 = 0, d3 = 0;
            mma_s8(d0, d1, d2, d3, A0[0], A1[0], A2[0], A3[0], wv.x, wv.y);
            mma_s8(d0, d1, d2, d3, A0[1], A1[1], A2[1], A3[1], wv.z, wv.w);
            mma_s8(d0, d1, d2, d3, A0[2], A1[2], A2[2], A3[2], wv2.x, wv2.y);

            const int cA = gct * 8 + 2 * tg, cB = cA + 1;
            const float alA = s_al[cA], bbA = s_bb[cA];
            const float alB = s_al[cB], bbB = s_bb[cB];
            signed char* ob = o_sm + wid * 512 + (gct & 3) * 128;
            ob[(2 * tg) * 16 + g]         = (signed char)requant_sat(d0, alA, bbA, C1);
            ob[(2 * tg + 1) * 16 + g]     = (signed char)requant_sat(d1, alB, bbB, C1);
            ob[(2 * tg) * 16 + g + 8]     = (signed char)requant_sat(d2, alA, bbA, C1);
            ob[(2 * tg + 1) * 16 + g + 8] = (signed char)requant_sat(d3, alB, bbB, C1);

            if ((gct & 3) == 3) {
                __syncwarp();
                int4 v = *(const int4*)(o_sm + wid * 512 + lane * 16);
                int tb = lane >> 3, col = lane & 7;
                int cog = (gct - 3 + tb) * 8 + col;
                *(int4*)(g_y1 + (size_t)(bw * CMID + cog) * HW_ + hww) = v;
                __syncwarp();
            }
        }
        rb = (rb == 2) ? 0 : rb + 1;
        lb = (lb == 2) ? 0 : lb + 1;
    }
}

// ---------------- k2: depthwise 3x3 -> interleaved g_y2i ----------------
__global__ void __launch_bounds__(256) k2_dw() {
    int t = blockIdx.x * 256 + threadIdx.x;
    int j = t & 3;
    int Q = t >> 2;
    int h = Q % 28;
    int bcg = Q / 28;
    int cg = bcg % 144;
    int b = bcg / 144;
    int c = 4 * cg + j;
    int base = (b * CMID + c) * HW_;

    int r0[8], r1[8], r2[8];
    const int* p1 = (const int*)(g_y1 + base + h * 28);
    #pragma unroll
    for (int q = 0; q < 7; ++q) r1[q] = p1[q];
    r1[7] = 0;
    if (h > 0) {
        const int* p0 = p1 - 7;
        #pragma unroll
        for (int q = 0; q < 7; ++q) r0[q] = p0[q];
    } else {
        #pragma unroll
        for (int q = 0; q < 7; ++q) r0[q] = 0;
    }
    r0[7] = 0;
    if (h < 27) {
        const int* p2 = p1 + 7;
        #pragma unroll
        for (int q = 0; q < 7; ++q) r2[q] = p2[q];
    } else {
        #pragma unroll
        for (int q = 0; q < 7; ++q) r2[q] = 0;
    }
    r2[7] = 0;

    int wp0 = g_w2p[c * 3 + 0];
    int wp1 = g_w2p[c * 3 + 1];
    int wp2 = g_w2p[c * 3 + 2];
    const float SIXTH = 1.0f / 6.0f;
    float al = (g_s[1] * g_ws2[c]) * SIXTH;
    float bb = g_bf2[c] * SIXTH;
    float C2 = 6.0f / g_s[2];

    int ow[7];
    int qv[4];
    #pragma unroll
    for (int w = 0; w < 28; ++w) {
        int op0, op1, op2;
        if (w == 0) {
            op0 = __byte_perm(r0[0], 0, 0x2104);
            op1 = __byte_perm(r1[0], 0, 0x2104);
            op2 = __byte_perm(r2[0], 0, 0x2104);
        } else {
            int s = w - 1, q = s >> 2, o = s & 3;
            unsigned sel = 0x3210u + (unsigned)o * 0x1111u;
            op0 = __byte_perm(r0[q], r0[q + 1], sel);
            op1 = __byte_perm(r1[q], r1[q + 1], sel);
            op2 = __byte_perm(r2[q], r2[q + 1], sel);
        }
        int acc = __dp4a(op0, wp0, __dp4a(op1, wp1, __dp4a(op2, wp2, 0)));
        qv[w & 3] = requant_sat(acc, al, bb, C2);
        if ((w & 3) == 3) {
            int lo = __byte_perm(qv[0], qv[1], 0x0040);
            int hi = __byte_perm(qv[2], qv[3], 0x0040);
            ow[w >> 2] = __byte_perm(lo, hi, 0x5410);
        }
    }

    int lane = threadIdx.x & 31;
    int qb = lane & ~3;
    int ob = (b * 144 + cg) * HW_ + h * 28;
    unsigned selj = (unsigned)j | ((unsigned)(j + 4) << 4);
    #pragma unroll
    for (int q = 0; q < 7; ++q) {
        int v0 = __shfl_sync(0xFFFFFFFFu, ow[q], qb + 0);
        int v1 = __shfl_sync(0xFFFFFFFFu, ow[q], qb + 1);
        int v2 = __shfl_sync(0xFFFFFFFFu, ow[q], qb + 2);
        int v3 = __shfl_sync(0xFFFFFFFFu, ow[q], qb + 3);
        int s1 = __byte_perm(v0, v1, selj);
        int s2 = __byte_perm(v2, v3, selj);
        g_y2i[ob + 4 * q + j] = __byte_perm(s1, s2, 0x5410);
    }
}

// ---------------- k3: 1x1 conv (576->96) IMMA, triple-buffered, 1 barrier/chunk ----------------
#define AS3 136
#define STG_STRIDE 132
__global__ void __launch_bounds__(256, 3) k3_conv3(const float* __restrict__ x,
                                                   float* __restrict__ out) {
    __shared__ union {
        struct {
            int a[3][16 * AS3];   // 26112 B
            int w[3][96 * 16];    // 18432 B
        } pipe;
        int stage[48 * STG_STRIDE];  // 25344 B (epilogue reuse)
    } sm;
    __shared__ float s_al[96], s_bb[96];

    const int tid = threadIdx.x, lane = tid & 31, wid = tid >> 5;
    const int g = lane >> 2, tg = lane & 3;
    const int n0 = blockIdx.x * 128;
    const int p0 = wid * 16;
    const float s3 = g_s[3], inv_s3 = 1.0f / s3;

    // prologue: chunks 0 and 1
    #pragma unroll
    for (int c0 = 0; c0 < 2; ++c0) {
        for (int idx = tid; idx < 512; idx += 256) {
            int r = idx >> 5, q4 = idx & 31;
            int n = n0 + 4 * q4, b = n / HW_, hw = n - b * HW_;
            CP16(smem_u32(&sm.pipe.a[c0][r * AS3 + 4 * q4]),
                 &g_y2i[(size_t)(b * 144 + c0 * 16 + r) * HW_ + hw]);
        }
        for (int idx = tid; idx < 384; idx += 256) {
            int co = idx >> 2, j = idx & 3;
            CP16(smem_u32(&sm.pipe.w[c0][co * 16 + 4 * j]),
                 &g_w3p[co * 144 + c0 * 16 + 4 * j]);
        }
        CP_COMMIT();
    }

    if (tid < 96) {
        s_al[tid] = (g_s[2] * g_ws3[tid]) * inv_s3;
        s_bb[tid] = g_bf3[tid] * inv_s3;
    }

    int acc[12][4];
    #pragma unroll
    for (int nt = 0; nt < 12; ++nt)
        #pragma unroll
        for (int q = 0; q < 4; ++q) acc[nt][q] = 0;

    int rb = 0, lb = 2;
    for (int kc = 0; kc < 9; ++kc) {        // 9 K-chunks of 64 channels
        if (kc < 8) { CP_WAIT1(); } else { CP_WAIT0(); }
        __syncthreads();
        if (kc + 2 <= 8) {
            for (int idx = tid; idx < 512; idx += 256) {
                int r = idx >> 5, q4 = idx & 31;
                int n = n0 + 4 * q4, b = n / HW_, hw = n - b * HW_;
                CP16(smem_u32(&sm.pipe.a[lb][r * AS3 + 4 * q4]),
                     &g_y2i[(size_t)(b * 144 + (kc + 2) * 16 + r) * HW_ + hw]);
            }
            for (int idx = tid; idx < 384; idx += 256) {
                int co = idx >> 2, j = idx & 3;
                CP16(smem_u32(&sm.pipe.w[lb][co * 16 + 4 * j]),
                     &g_w3p[co * 144 + (kc + 2) * 16 + 4 * j]);
            }
            CP_COMMIT();
        }
        const int* ab = sm.pipe.a[rb];
        const int* wb = sm.pipe.w[rb];

        int a00 = ab[tg * AS3 + p0 + g];
        int a01 = ab[tg * AS3 + p0 + g + 8];
        int a02 = ab[(4 + tg) * AS3 + p0 + g];
        int a03 = ab[(4 + tg) * AS3 + p0 + g + 8];
        int a10 = ab[(8 + tg) * AS3 + p0 + g];
        int a11 = ab[(8 + tg) * AS3 + p0 + g + 8];
        int a12 = ab[(12 + tg) * AS3 + p0 + g];
        int a13 = ab[(12 + tg) * AS3 + p0 + g + 8];

        #pragma unroll
        for (int nt = 0; nt < 12; ++nt) {
            int4 wv = *(const int4*)&wb[(8 * nt + g) * 16 + tg * 4];
            mma_s8(acc[nt][0], acc[nt][1], acc[nt][2], acc[nt][3],
                   a00, a01, a02, a03, wv.x, wv.y);
            mma_s8(acc[nt][0], acc[nt][1], acc[nt][2], acc[nt][3],
                   a10, a11, a12, a13, wv.z, wv.w);
        }
        rb = (rb == 2) ? 0 : rb + 1;
        lb = (lb == 2) ? 0 : lb + 1;
    }

    // ---- staged, coalesced epilogue: 2 rounds of 48 channels ----
    #pragma unroll
    for (int r = 0; r < 2; ++r) {
        __syncthreads();
        #pragma unroll
        for (int i = 0; i < 6; ++i) {
            int nt = 6 * r + i;
            int cl0 = 8 * i + 2 * tg;
            sm.stage[cl0 * STG_STRIDE + p0 + g]           = acc[nt][0];
            sm.stage[(cl0 + 1) * STG_STRIDE + p0 + g]     = acc[nt][1];
            sm.stage[cl0 * STG_STRIDE + p0 + g + 8]       = acc[nt][2];
            sm.stage[(cl0 + 1) * STG_STRIDE + p0 + g + 8] = acc[nt][3];
        }
        __syncthreads();
        int n = n0 + 4 * lane;
        int b = n / HW_;
        int hw = n - b * HW_;
        #pragma unroll
        for (int i = 0; i < 6; ++i) {
            int cl = 6 * wid + i;
            int c = 48 * r + cl;
            const int4 v = *(const int4*)&sm.stage[cl * STG_STRIDE + 4 * lane];
            const float al = s_al[c], bb = s_bb[c];
            size_t off = (size_t)(b * COUT + c) * HW_ + hw;
            float4 xv = *(const float4*)(x + off);
            float t0, q0, t1, q1, t2, q2, t3, q3;
            t0 = fmaf((float)v.x, al, bb); t0 = fmaf(xv.x, inv_s3, t0);
            q0 = rintf(fminf(fmaxf(t0, -127.f), 127.f));
            t1 = fmaf((float)v.y, al, bb); t1 = fmaf(xv.y, inv_s3, t1);
            q1 = rintf(fminf(fmaxf(t1, -127.f), 127.f));
            t2 = fmaf((float)v.z, al, bb); t2 = fmaf(xv.z, inv_s3, t2);
            q2 = rintf(fminf(fmaxf(t2, -127.f), 127.f));
            t3 = fmaf((float)v.w, al, bb); t3 = fmaf(xv.w, inv_s3, t3);
            q3 = rintf(fminf(fmaxf(t3, -127.f), 127.f));
            *(float4*)(out + off) = make_float4(q0 * s3, q1 * s3, q2 * s3, q3 * s3);
        }
    }
}

// ---------------- launch ----------------
extern "C" void kernel_launch(void* const* d_in, const int* in_sizes, int n_in,
                              void* d_out, int out_size) {
    const float* x  = (const float*)d_in[0];
    const float* w1 = (const float*)d_in[1];
    const float* g1 = (const float*)d_in[2];
    const float* b1 = (const float*)d_in[3];
    const float* m1 = (const float*)d_in[4];
    const float* v1 = (const float*)d_in[5];
    const float* w2 = (const float*)d_in[6];
    const float* g2 = (const float*)d_in[7];
    const float* b2 = (const float*)d_in[8];
    const float* m2 = (const float*)d_in[9];
    const float* v2 = (const float*)d_in[10];
    const float* w3 = (const float*)d_in[11];
    const float* g3 = (const float*)d_in[12];
    const float* b3 = (const float*)d_in[13];
    const float* m3 = (const float*)d_in[14];
    const float* v3 = (const float*)d_in[15];
    const float* r0 = (const float*)d_in[16];
    const float* r1 = (const float*)d_in[17];
    const float* r2 = (const float*)d_in[18];
    const float* r3 = (const float*)d_in[19];
    const int*   cl = (const int*)d_in[20];

    float* out = (float*)d_out;
    const int NOUT = B_ * COUT * HW_;
    float* s3out = (out_size > NOUT) ? out + NOUT : nullptr;

    cudaFuncSetAttribute(k1_conv1, cudaFuncAttributePreferredSharedMemoryCarveout, 70);
    cudaFuncSetAttribute(k3_conv3, cudaFuncAttributePreferredSharedMemoryCarveout, 70);

    prep_all<<<156, 256>>>(w1, g1, b1, m1, v1,
                           w2, g2, b2, m2, v2,
                           w3, g3, b3, m3, v3,
                           r0, r1, r2, r3, cl, s3out);
    k1_conv1<<<NPIX / 128, 256>>>(x);
    k2_dw<<<(B_ * CMID * 28) / 256, 256>>>();
    k3_conv3<<<NPIX / 128, 256>>>(x, out);
}